// round 3
// baseline (speedup 1.0000x reference)
#include <cuda_runtime.h>
#include <cstdint>

// Problem dims (fixed by the reference generator)
#define N_MAX   100000
#define IN_DIM  128

// Scratch: static device arrays (no allocation allowed)
__device__ float g_h[(size_t)N_MAX * 128];    // per-layer pre-aggregation features (reused for layer2)
__device__ float g_agg[(size_t)N_MAX * 128];  // layer-1 aggregate
__device__ float g_dinv[N_MAX];               // deg -> rsqrt(deg)

// ---------------------------------------------------------------------------
// small elementwise kernels
// ---------------------------------------------------------------------------
__global__ void fill_kernel(float* __restrict__ p, float v, int n) {
    int i = blockIdx.x * blockDim.x + threadIdx.x;
    if (i < n) p[i] = v;
}

__global__ void deg_kernel(const int* __restrict__ dst, float* __restrict__ deg, int E) {
    int e = blockIdx.x * blockDim.x + threadIdx.x;
    if (e < E) atomicAdd(&deg[dst[e]], 1.0f);
}

__global__ void rsqrt_kernel(float* __restrict__ p, int n) {
    int i = blockIdx.x * blockDim.x + threadIdx.x;
    if (i < n) p[i] = rsqrtf(p[i]);
}

// out[i*F+f] = h[i*F+f] * dinv[i]^2   (self-loop message; also initializes out)
template<int F>
__global__ void self_init_kernel(const float* __restrict__ h, const float* __restrict__ dinv,
                                 float* __restrict__ out, int N) {
    size_t i = (size_t)blockIdx.x * blockDim.x + threadIdx.x;
    if (i >= (size_t)N * F) return;
    int node = (int)(i / F);
    float di = __ldg(&dinv[node]);
    out[i] = h[i] * di * di;
}

__global__ void bias_relu_kernel(float* __restrict__ out, const float* __restrict__ b,
                                 int N, int F) {
    size_t i = (size_t)blockIdx.x * blockDim.x + threadIdx.x;
    if (i >= (size_t)N * F) return;
    int f = (int)(i % F);
    out[i] = fmaxf(out[i] + b[f], 0.0f);
}

// ---------------------------------------------------------------------------
// GEMM: C[N,F] = act(A[N,K]) @ W[K,F]
//   PRELU: act(a) = relu(a + bias[k])  (bias indexed by K / input feature)
// Block: 256 threads, tile = 64 rows x F cols, per-thread microtile 8 x VEC.
// A tile staged in smem; W streamed from L1 (64KB, fully cache-resident).
// ---------------------------------------------------------------------------
template<int K, int F, int VEC, bool PRELU>
__global__ __launch_bounds__(256)
void gemm_kernel(const float* __restrict__ A, const float* __restrict__ W,
                 const float* __restrict__ bias, float* __restrict__ C, int N) {
    __shared__ float xs[64][K];
    const int row0 = blockIdx.x * 64;
    const int tid  = threadIdx.x;

    // stage A tile (vectorized, zero-fill OOB rows, optional fused relu(+b))
    const int TOT4 = 64 * K / 4;
    for (int i = tid; i < TOT4; i += 256) {
        int fidx = i * 4;
        int r = fidx / K, k = fidx % K;
        float4 v;
        if (row0 + r < N) v = *(const float4*)&A[(size_t)(row0 + r) * K + k];
        else              v = make_float4(0.f, 0.f, 0.f, 0.f);
        if (PRELU) {
            v.x = fmaxf(v.x + bias[k + 0], 0.f);
            v.y = fmaxf(v.y + bias[k + 1], 0.f);
            v.z = fmaxf(v.z + bias[k + 2], 0.f);
            v.w = fmaxf(v.w + bias[k + 3], 0.f);
        }
        *(float4*)&xs[r][k] = v;
    }
    __syncthreads();

    const int tx = tid & 31;   // column group
    const int ty = tid >> 5;   // row group (8 groups x 8 rows)

    float acc[8][VEC];
    #pragma unroll
    for (int r = 0; r < 8; r++)
        #pragma unroll
        for (int c = 0; c < VEC; c++) acc[r][c] = 0.f;

    #pragma unroll 4
    for (int k = 0; k < K; k++) {
        float w[VEC];
        if (VEC == 4) {
            float4 t = *(const float4*)&W[(size_t)k * F + tx * 4];
            w[0] = t.x; w[1] = t.y; w[2] = t.z; w[3] = t.w;
        } else {
            float2 t = *(const float2*)&W[(size_t)k * F + tx * 2];
            w[0] = t.x; w[1] = t.y;
        }
        #pragma unroll
        for (int r = 0; r < 8; r++) {
            float xv = xs[ty * 8 + r][k];   // warp-broadcast LDS
            #pragma unroll
            for (int c = 0; c < VEC; c++) acc[r][c] += xv * w[c];
        }
    }

    #pragma unroll
    for (int r = 0; r < 8; r++) {
        int row = row0 + ty * 8 + r;
        if (row < N) {
            #pragma unroll
            for (int c = 0; c < VEC; c++)
                C[(size_t)row * F + tx * VEC + c] = acc[r][c];
        }
    }
}

// ---------------------------------------------------------------------------
// Edge scatter: one warp per edge.
//   out[dst] += h[src] * dinv[src]*dinv[dst]
// h + out together ~102MB -> mostly L2-resident on B200 (~126MB L2).
// ---------------------------------------------------------------------------
template<int F>
__global__ __launch_bounds__(256)
void scatter_kernel(const float* __restrict__ h,
                    const int* __restrict__ src,
                    const int* __restrict__ dst,
                    const float* __restrict__ dinv,
                    float* __restrict__ out, int E) {
    long long gid = (long long)blockIdx.x * blockDim.x + threadIdx.x;
    int e = (int)(gid >> 5);
    int lane = (int)(gid & 31);
    if (e >= E) return;
    int s = __ldg(&src[e]);   // same addr across warp -> broadcast
    int d = __ldg(&dst[e]);
    float c = __ldg(&dinv[s]) * __ldg(&dinv[d]);
    const float* hp = h + (size_t)s * F;
    float*       op = out + (size_t)d * F;
    #pragma unroll
    for (int f = lane; f < F; f += 32)
        atomicAdd(op + f, hp[f] * c);
}

// ---------------------------------------------------------------------------
// launch
// ---------------------------------------------------------------------------
extern "C" void kernel_launch(void* const* d_in, const int* in_sizes, int n_in,
                              void* d_out, int out_size) {
    const float* x  = (const float*)d_in[0];   // [N,128]
    const int*   ei = (const int*)d_in[1];     // [2,E] int32 (JAX default: x64 disabled)
    const float* W1 = (const float*)d_in[2];   // [128,128]
    const float* b1 = (const float*)d_in[3];   // [128]
    const float* W2 = (const float*)d_in[4];   // [128,64]
    const float* b2 = (const float*)d_in[5];   // [64]
    float*       out = (float*)d_out;          // [N,64]

    const int N = in_sizes[0] / IN_DIM;
    const int E = in_sizes[1] / 2;
    (void)n_in; (void)out_size;

    void* p;
    cudaGetSymbolAddress(&p, g_h);    float* h    = (float*)p;
    cudaGetSymbolAddress(&p, g_agg);  float* agg  = (float*)p;
    cudaGetSymbolAddress(&p, g_dinv); float* dinv = (float*)p;

    const int* src = ei;
    const int* dst = ei + E;

    // --- symmetric normalization: dinv = rsqrt(in-degree + 1) ---
    fill_kernel<<<(N + 255) / 256, 256>>>(dinv, 1.0f, N);
    deg_kernel<<<(E + 255) / 256, 256>>>(dst, dinv, E);
    rsqrt_kernel<<<(N + 255) / 256, 256>>>(dinv, N);

    // --- layer 1: h = x @ W1 ; agg = scatter(h) ; (bias+relu fused into layer-2 gemm load) ---
    gemm_kernel<128, 128, 4, false><<<(N + 63) / 64, 256>>>(x, W1, nullptr, h, N);
    self_init_kernel<128><<<(int)(((size_t)N * 128 + 255) / 256), 256>>>(h, dinv, agg, N);
    scatter_kernel<128><<<(int)(((long long)E * 32 + 255) / 256), 256>>>(h, src, dst, dinv, agg, E);

    // --- layer 2: h2 = relu(agg + b1) @ W2 (fused) ; out = scatter(h2) ; relu(out + b2) ---
    gemm_kernel<128, 64, 2, true><<<(N + 63) / 64, 256>>>(agg, W2, b1, h, N);
    self_init_kernel<64><<<(int)(((size_t)N * 64 + 255) / 256), 256>>>(h, dinv, out, N);
    scatter_kernel<64><<<(int)(((long long)E * 32 + 255) / 256), 256>>>(h, src, dst, dinv, out, E);
    bias_relu_kernel<<<(int)(((size_t)N * 64 + 255) / 256), 256>>>(out, b2, N, 64);
}

// round 5
// speedup vs baseline: 2.1216x; 2.1216x over previous
#include <cuda_runtime.h>
#include <cstdint>

#define N_MAX   100000
#define E_MAX   1600000
#define IN_DIM  128
#define SCAN_B  1024

// static scratch (no allocation allowed)
__device__ float g_h[(size_t)N_MAX * 128];     // pre-aggregation features (h_norm), reused per layer
__device__ float g_agg[(size_t)N_MAX * 128];   // layer-1 aggregate
__device__ float g_dinv[N_MAX];
__device__ int   g_deg[N_MAX];
__device__ int   g_offs[N_MAX + 1];
__device__ int   g_cursor[N_MAX];
__device__ int   g_csr_src[E_MAX];
__device__ int   g_blocksums[(N_MAX + SCAN_B - 1) / SCAN_B + 1];

// ---------------------------------------------------------------------------
// CSR build: histogram -> scan -> bin fill
// ---------------------------------------------------------------------------
__global__ void zero_int_kernel(int* __restrict__ p, int n) {
    int i = blockIdx.x * blockDim.x + threadIdx.x;
    if (i < n) p[i] = 0;
}

__global__ void deg_kernel(const int* __restrict__ dst, int* __restrict__ deg, int E) {
    int e = blockIdx.x * blockDim.x + threadIdx.x;
    if (e < E) atomicAdd(&deg[dst[e]], 1);
}

__global__ void dinv_kernel(const int* __restrict__ deg, float* __restrict__ dinv, int N) {
    int i = blockIdx.x * blockDim.x + threadIdx.x;
    if (i < N) dinv[i] = rsqrtf((float)(deg[i] + 1));   // +1 self-loop
}

__global__ void scan_block_kernel(const int* __restrict__ deg, int* __restrict__ offs,
                                  int* __restrict__ blocksums, int N) {
    __shared__ int sh[SCAN_B];
    int i = blockIdx.x * SCAN_B + threadIdx.x;
    int v = (i < N) ? deg[i] : 0;
    sh[threadIdx.x] = v; __syncthreads();
    for (int off = 1; off < SCAN_B; off <<= 1) {
        int t = (threadIdx.x >= off) ? sh[threadIdx.x - off] : 0;
        __syncthreads();
        sh[threadIdx.x] += t;
        __syncthreads();
    }
    if (i < N) offs[i] = sh[threadIdx.x] - v;           // exclusive
    if (threadIdx.x == SCAN_B - 1) blocksums[blockIdx.x] = sh[threadIdx.x];
}

__global__ void scan_sums_kernel(int* __restrict__ blocksums, int nb) {
    __shared__ int sh[SCAN_B];
    int v = (threadIdx.x < nb) ? blocksums[threadIdx.x] : 0;
    sh[threadIdx.x] = v; __syncthreads();
    for (int off = 1; off < SCAN_B; off <<= 1) {
        int t = (threadIdx.x >= off) ? sh[threadIdx.x - off] : 0;
        __syncthreads();
        sh[threadIdx.x] += t;
        __syncthreads();
    }
    if (threadIdx.x < nb) blocksums[threadIdx.x] = sh[threadIdx.x] - v;  // exclusive
}

__global__ void scan_add_kernel(int* __restrict__ offs, const int* __restrict__ blocksums,
                                int* __restrict__ cursor, int N, int E) {
    int i = blockIdx.x * blockDim.x + threadIdx.x;
    if (i < N) {
        int o = offs[i] + blocksums[i / SCAN_B];
        offs[i] = o;
        cursor[i] = o;
    }
    if (i == 0) offs[N] = E;
}

__global__ void binfill_kernel(const int* __restrict__ src, const int* __restrict__ dst,
                               int* __restrict__ cursor, int* __restrict__ csr_src, int E) {
    int e = blockIdx.x * blockDim.x + threadIdx.x;
    if (e < E) {
        int d = dst[e];
        int p = atomicAdd(&cursor[d], 1);
        csr_src[p] = src[e];
    }
}

// ---------------------------------------------------------------------------
// GEMM: C[N,F] = act(A[N,K]) @ W[K,F], epilogue scales row by dinv[row].
//   PRELU: act(a) = relu(a + biasK[k])  (input-feature bias, layer fusion)
// 256 thr, tile 64 rows x F cols, microtile 8 x VEC, k-blocked by 4 for ILP.
// ---------------------------------------------------------------------------
template<int K, int F, int VEC, bool PRELU>
__global__ __launch_bounds__(256)
void gemm_kernel(const float* __restrict__ A, const float* __restrict__ W,
                 const float* __restrict__ biasK, const float* __restrict__ dinv,
                 float* __restrict__ C, int N) {
    __shared__ float xs[64][K];
    const int row0 = blockIdx.x * 64;
    const int tid  = threadIdx.x;

    const int TOT4 = 64 * K / 4;
    for (int i = tid; i < TOT4; i += 256) {
        int fidx = i * 4;
        int r = fidx / K, k = fidx % K;
        float4 v;
        if (row0 + r < N) v = *(const float4*)&A[(size_t)(row0 + r) * K + k];
        else              v = make_float4(0.f, 0.f, 0.f, 0.f);
        if (PRELU) {
            v.x = fmaxf(v.x + biasK[k + 0], 0.f);
            v.y = fmaxf(v.y + biasK[k + 1], 0.f);
            v.z = fmaxf(v.z + biasK[k + 2], 0.f);
            v.w = fmaxf(v.w + biasK[k + 3], 0.f);
        }
        *(float4*)&xs[r][k] = v;
    }
    __syncthreads();

    const int tx = tid & 31;
    const int ty = tid >> 5;

    float acc[8][VEC];
    #pragma unroll
    for (int r = 0; r < 8; r++)
        #pragma unroll
        for (int c = 0; c < VEC; c++) acc[r][c] = 0.f;

    for (int k = 0; k < K; k += 4) {
        float w[4][VEC];
        #pragma unroll
        for (int kk = 0; kk < 4; kk++) {
            if (VEC == 4) {
                float4 t = *(const float4*)&W[(size_t)(k + kk) * F + tx * 4];
                w[kk][0] = t.x; w[kk][1] = t.y; w[kk][2] = t.z; w[kk][3] = t.w;
            } else {
                float2 t = *(const float2*)&W[(size_t)(k + kk) * F + tx * 2];
                w[kk][0] = t.x; w[kk][1] = t.y;
            }
        }
        #pragma unroll
        for (int r = 0; r < 8; r++) {
            float4 xv = *(const float4*)&xs[ty * 8 + r][k];   // broadcast LDS.128
            #pragma unroll
            for (int c = 0; c < VEC; c++) {
                acc[r][c] += xv.x * w[0][c];
                acc[r][c] += xv.y * w[1][c];
                acc[r][c] += xv.z * w[2][c];
                acc[r][c] += xv.w * w[3][c];
            }
        }
    }

    #pragma unroll
    for (int r = 0; r < 8; r++) {
        int row = row0 + ty * 8 + r;
        if (row < N) {
            float di = __ldg(&dinv[row]);
            #pragma unroll
            for (int c = 0; c < VEC; c++)
                C[(size_t)row * F + tx * VEC + c] = acc[r][c] * di;
        }
    }
}

// ---------------------------------------------------------------------------
// CSR gather, layer 1 (F=128): agg[d] = dinv[d] * (hn[d] + sum_s hn[s])
// one warp per node, lane handles 4 features (float4)
// ---------------------------------------------------------------------------
__global__ __launch_bounds__(256)
void gather128_kernel(const float* __restrict__ hn, const int* __restrict__ offs,
                      const int* __restrict__ csr, const float* __restrict__ dinv,
                      float* __restrict__ out, int N) {
    int warp = (blockIdx.x * 256 + threadIdx.x) >> 5;
    int lane = threadIdx.x & 31;
    if (warp >= N) return;
    const int row = warp;
    int beg = __ldg(&offs[row]);
    int end = __ldg(&offs[row + 1]);
    float di = __ldg(&dinv[row]);

    float4 acc = *(const float4*)&hn[(size_t)row * 128 + lane * 4];  // self-loop
    int j = beg;
    for (; j + 1 < end; j += 2) {
        int s0 = __ldg(&csr[j]);
        int s1 = __ldg(&csr[j + 1]);
        float4 v0 = *(const float4*)&hn[(size_t)s0 * 128 + lane * 4];
        float4 v1 = *(const float4*)&hn[(size_t)s1 * 128 + lane * 4];
        acc.x += v0.x; acc.y += v0.y; acc.z += v0.z; acc.w += v0.w;
        acc.x += v1.x; acc.y += v1.y; acc.z += v1.z; acc.w += v1.w;
    }
    if (j < end) {
        int s = __ldg(&csr[j]);
        float4 v = *(const float4*)&hn[(size_t)s * 128 + lane * 4];
        acc.x += v.x; acc.y += v.y; acc.z += v.z; acc.w += v.w;
    }
    acc.x *= di; acc.y *= di; acc.z *= di; acc.w *= di;
    *(float4*)&out[(size_t)row * 128 + lane * 4] = acc;
}

// ---------------------------------------------------------------------------
// CSR gather, layer 2 (F=64) + final bias/relu:
//   out[d] = relu(dinv[d] * (hn[d] + sum_s hn[s]) + b2)
// lane handles 2 features (float2)
// ---------------------------------------------------------------------------
__global__ __launch_bounds__(256)
void gather64_kernel(const float* __restrict__ hn, const int* __restrict__ offs,
                     const int* __restrict__ csr, const float* __restrict__ dinv,
                     const float* __restrict__ b2, float* __restrict__ out, int N) {
    int warp = (blockIdx.x * 256 + threadIdx.x) >> 5;
    int lane = threadIdx.x & 31;
    if (warp >= N) return;
    const int row = warp;
    int beg = __ldg(&offs[row]);
    int end = __ldg(&offs[row + 1]);
    float di = __ldg(&dinv[row]);

    float2 acc = *(const float2*)&hn[(size_t)row * 64 + lane * 2];   // self-loop
    int j = beg;
    for (; j + 1 < end; j += 2) {
        int s0 = __ldg(&csr[j]);
        int s1 = __ldg(&csr[j + 1]);
        float2 v0 = *(const float2*)&hn[(size_t)s0 * 64 + lane * 2];
        float2 v1 = *(const float2*)&hn[(size_t)s1 * 64 + lane * 2];
        acc.x += v0.x; acc.y += v0.y;
        acc.x += v1.x; acc.y += v1.y;
    }
    if (j < end) {
        int s = __ldg(&csr[j]);
        float2 v = *(const float2*)&hn[(size_t)s * 64 + lane * 2];
        acc.x += v.x; acc.y += v.y;
    }
    float2 bb = *(const float2*)&b2[lane * 2];
    acc.x = fmaxf(acc.x * di + bb.x, 0.f);
    acc.y = fmaxf(acc.y * di + bb.y, 0.f);
    *(float2*)&out[(size_t)row * 64 + lane * 2] = acc;
}

// ---------------------------------------------------------------------------
extern "C" void kernel_launch(void* const* d_in, const int* in_sizes, int n_in,
                              void* d_out, int out_size) {
    const float* x  = (const float*)d_in[0];
    const int*   ei = (const int*)d_in[1];     // int32 (JAX x64 disabled)
    const float* W1 = (const float*)d_in[2];
    const float* b1 = (const float*)d_in[3];
    const float* W2 = (const float*)d_in[4];
    const float* b2 = (const float*)d_in[5];
    float*       out = (float*)d_out;

    const int N = in_sizes[0] / IN_DIM;
    const int E = in_sizes[1] / 2;
    (void)n_in; (void)out_size;

    void* p;
    cudaGetSymbolAddress(&p, g_h);        float* h    = (float*)p;
    cudaGetSymbolAddress(&p, g_agg);      float* agg  = (float*)p;
    cudaGetSymbolAddress(&p, g_dinv);     float* dinv = (float*)p;
    cudaGetSymbolAddress(&p, g_deg);      int* deg    = (int*)p;
    cudaGetSymbolAddress(&p, g_offs);     int* offs   = (int*)p;
    cudaGetSymbolAddress(&p, g_cursor);   int* cursor = (int*)p;
    cudaGetSymbolAddress(&p, g_csr_src);  int* csr    = (int*)p;
    cudaGetSymbolAddress(&p, g_blocksums);int* bsums  = (int*)p;

    const int* src = ei;
    const int* dst = ei + E;
    const int nb = (N + SCAN_B - 1) / SCAN_B;

    // --- CSR build + normalization ---
    zero_int_kernel<<<(N + 255) / 256, 256>>>(deg, N);
    deg_kernel<<<(E + 255) / 256, 256>>>(dst, deg, E);
    dinv_kernel<<<(N + 255) / 256, 256>>>(deg, dinv, N);
    scan_block_kernel<<<nb, SCAN_B>>>(deg, offs, bsums, N);
    scan_sums_kernel<<<1, SCAN_B>>>(bsums, nb);
    scan_add_kernel<<<(N + 255) / 256, 256>>>(offs, bsums, cursor, N, E);
    binfill_kernel<<<(E + 255) / 256, 256>>>(src, dst, cursor, csr, E);

    // --- layer 1: hn = (x @ W1) * dinv ; agg = dinv * (self + gather) ---
    gemm_kernel<128, 128, 4, false><<<(N + 63) / 64, 256>>>(x, W1, nullptr, dinv, h, N);
    gather128_kernel<<<(N * 32 + 255) / 256, 256>>>(h, offs, csr, dinv, agg, N);

    // --- layer 2: hn2 = (relu(agg + b1) @ W2) * dinv ; out = relu(dinv*(self+gather) + b2) ---
    gemm_kernel<128, 64, 2, true><<<(N + 63) / 64, 256>>>(agg, W2, b1, dinv, h, N);
    gather64_kernel<<<(N * 32 + 255) / 256, 256>>>(h, offs, csr, dinv, b2, out, N);
}

// round 6
// speedup vs baseline: 2.3606x; 1.1127x over previous
#include <cuda_runtime.h>
#include <cuda_fp16.h>
#include <cstdint>

#define N_MAX   100000
#define E_MAX   1600000
#define IN_DIM  128
#define SCAN_B  1024

// static scratch (no allocation allowed)
__device__ float g_h[(size_t)N_MAX * 128];     // layer1: fp16 h_norm (N x 128 half); layer2: fp32 h_norm (N x 64)
__device__ float g_agg[(size_t)N_MAX * 128];   // layer-1 aggregate (fp32)
__device__ float g_dinv[N_MAX];
__device__ int   g_deg[N_MAX];
__device__ int   g_offs[N_MAX + 1];
__device__ int   g_cursor[N_MAX];
__device__ int   g_csr_src[E_MAX];
__device__ int   g_blocksums[(N_MAX + SCAN_B - 1) / SCAN_B + 1];

// ---------------------------------------------------------------------------
// CSR build: histogram -> scan (fused dinv) -> bin fill
// ---------------------------------------------------------------------------
__global__ void zero_int_kernel(int* __restrict__ p, int n) {
    int i = blockIdx.x * blockDim.x + threadIdx.x;
    if (i < n) p[i] = 0;
}

__global__ void deg_kernel(const int* __restrict__ dst, int* __restrict__ deg, int E) {
    int e = blockIdx.x * blockDim.x + threadIdx.x;
    if (e < E) atomicAdd(&deg[dst[e]], 1);
}

__global__ void scan_block_kernel(const int* __restrict__ deg, int* __restrict__ offs,
                                  int* __restrict__ blocksums, float* __restrict__ dinv, int N) {
    __shared__ int sh[SCAN_B];
    int i = blockIdx.x * SCAN_B + threadIdx.x;
    int v = (i < N) ? deg[i] : 0;
    if (i < N) dinv[i] = rsqrtf((float)(v + 1));        // fused: rsqrt(deg + self-loop)
    sh[threadIdx.x] = v; __syncthreads();
    for (int off = 1; off < SCAN_B; off <<= 1) {
        int t = (threadIdx.x >= off) ? sh[threadIdx.x - off] : 0;
        __syncthreads();
        sh[threadIdx.x] += t;
        __syncthreads();
    }
    if (i < N) offs[i] = sh[threadIdx.x] - v;           // exclusive
    if (threadIdx.x == SCAN_B - 1) blocksums[blockIdx.x] = sh[threadIdx.x];
}

__global__ void scan_sums_kernel(int* __restrict__ blocksums, int nb) {
    __shared__ int sh[SCAN_B];
    int v = (threadIdx.x < nb) ? blocksums[threadIdx.x] : 0;
    sh[threadIdx.x] = v; __syncthreads();
    for (int off = 1; off < SCAN_B; off <<= 1) {
        int t = (threadIdx.x >= off) ? sh[threadIdx.x - off] : 0;
        __syncthreads();
        sh[threadIdx.x] += t;
        __syncthreads();
    }
    if (threadIdx.x < nb) blocksums[threadIdx.x] = sh[threadIdx.x] - v;  // exclusive
}

__global__ void scan_add_kernel(int* __restrict__ offs, const int* __restrict__ blocksums,
                                int* __restrict__ cursor, int N, int E) {
    int i = blockIdx.x * blockDim.x + threadIdx.x;
    if (i < N) {
        int o = offs[i] + blocksums[i / SCAN_B];
        offs[i] = o;
        cursor[i] = o;
    }
    if (i == 0) offs[N] = E;
}

__global__ void binfill_kernel(const int* __restrict__ src, const int* __restrict__ dst,
                               int* __restrict__ cursor, int* __restrict__ csr_src, int E) {
    int e = blockIdx.x * blockDim.x + threadIdx.x;
    if (e < E) {
        int d = dst[e];
        int p = atomicAdd(&cursor[d], 1);
        csr_src[p] = src[e];
    }
}

// ---------------------------------------------------------------------------
// GEMM: C[N,F] = act(A[N,K]) @ W[K,F], epilogue scales row by dinv[row].
//   PRELU: act(a) = relu(a + biasK[k]);  OUTH: emit __half (half2-packed)
// ---------------------------------------------------------------------------
template<int K, int F, int VEC, bool PRELU, bool OUTH>
__global__ __launch_bounds__(256)
void gemm_kernel(const float* __restrict__ A, const float* __restrict__ W,
                 const float* __restrict__ biasK, const float* __restrict__ dinv,
                 void* __restrict__ Cout, int N) {
    __shared__ float xs[64][K];
    const int row0 = blockIdx.x * 64;
    const int tid  = threadIdx.x;

    const int TOT4 = 64 * K / 4;
    for (int i = tid; i < TOT4; i += 256) {
        int fidx = i * 4;
        int r = fidx / K, k = fidx % K;
        float4 v;
        if (row0 + r < N) v = *(const float4*)&A[(size_t)(row0 + r) * K + k];
        else              v = make_float4(0.f, 0.f, 0.f, 0.f);
        if (PRELU) {
            v.x = fmaxf(v.x + biasK[k + 0], 0.f);
            v.y = fmaxf(v.y + biasK[k + 1], 0.f);
            v.z = fmaxf(v.z + biasK[k + 2], 0.f);
            v.w = fmaxf(v.w + biasK[k + 3], 0.f);
        }
        *(float4*)&xs[r][k] = v;
    }
    __syncthreads();

    const int tx = tid & 31;
    const int ty = tid >> 5;

    float acc[8][VEC];
    #pragma unroll
    for (int r = 0; r < 8; r++)
        #pragma unroll
        for (int c = 0; c < VEC; c++) acc[r][c] = 0.f;

    for (int k = 0; k < K; k += 4) {
        float w[4][VEC];
        #pragma unroll
        for (int kk = 0; kk < 4; kk++) {
            if (VEC == 4) {
                float4 t = *(const float4*)&W[(size_t)(k + kk) * F + tx * 4];
                w[kk][0] = t.x; w[kk][1] = t.y; w[kk][2] = t.z; w[kk][3] = t.w;
            } else {
                float2 t = *(const float2*)&W[(size_t)(k + kk) * F + tx * 2];
                w[kk][0] = t.x; w[kk][1] = t.y;
            }
        }
        #pragma unroll
        for (int r = 0; r < 8; r++) {
            float4 xv = *(const float4*)&xs[ty * 8 + r][k];   // broadcast LDS.128
            #pragma unroll
            for (int c = 0; c < VEC; c++) {
                acc[r][c] += xv.x * w[0][c];
                acc[r][c] += xv.y * w[1][c];
                acc[r][c] += xv.z * w[2][c];
                acc[r][c] += xv.w * w[3][c];
            }
        }
    }

    #pragma unroll
    for (int r = 0; r < 8; r++) {
        int row = row0 + ty * 8 + r;
        if (row < N) {
            float di = __ldg(&dinv[row]);
            if (OUTH) {
                // VEC must be 4 here: 4 floats -> 2 half2 -> 8B store
                __half2 h0 = __floats2half2_rn(acc[r][0] * di, acc[r][1] * di);
                __half2 h1 = __floats2half2_rn(acc[r][2] * di, acc[r][3] * di);
                uint2 st;
                st.x = *(uint32_t*)&h0;
                st.y = *(uint32_t*)&h1;
                *(uint2*)((__half*)Cout + (size_t)row * F + tx * VEC) = st;
            } else {
                float* C = (float*)Cout;
                #pragma unroll
                for (int c = 0; c < VEC; c++)
                    C[(size_t)row * F + tx * VEC + c] = acc[r][c] * di;
            }
        }
    }
}

// ---------------------------------------------------------------------------
// CSR gather, layer 1 (F=128, fp16 input): agg[d] = dinv[d] * (hn[d] + sum hn[s])
// one warp per node; lane handles 4 halves (8B); fp32 accumulate; unroll 4.
// ---------------------------------------------------------------------------
__device__ __forceinline__ void add_h4(float4& acc, uint2 v) {
    __half2 a = *(__half2*)&v.x;
    __half2 b = *(__half2*)&v.y;
    float2 fa = __half22float2(a);
    float2 fb = __half22float2(b);
    acc.x += fa.x; acc.y += fa.y; acc.z += fb.x; acc.w += fb.y;
}

__global__ __launch_bounds__(256)
void gather128h_kernel(const __half* __restrict__ hn, const int* __restrict__ offs,
                       const int* __restrict__ csr, const float* __restrict__ dinv,
                       float* __restrict__ out, int N) {
    int warp = (blockIdx.x * 256 + threadIdx.x) >> 5;
    int lane = threadIdx.x & 31;
    if (warp >= N) return;
    const int row = warp;
    int beg = __ldg(&offs[row]);
    int end = __ldg(&offs[row + 1]);
    float di = __ldg(&dinv[row]);

    float4 acc = make_float4(0.f, 0.f, 0.f, 0.f);
    add_h4(acc, *(const uint2*)(hn + (size_t)row * 128 + lane * 4));   // self-loop

    int j = beg;
    for (; j + 3 < end; j += 4) {
        int s0 = __ldg(&csr[j + 0]);
        int s1 = __ldg(&csr[j + 1]);
        int s2 = __ldg(&csr[j + 2]);
        int s3 = __ldg(&csr[j + 3]);
        uint2 v0 = *(const uint2*)(hn + (size_t)s0 * 128 + lane * 4);
        uint2 v1 = *(const uint2*)(hn + (size_t)s1 * 128 + lane * 4);
        uint2 v2 = *(const uint2*)(hn + (size_t)s2 * 128 + lane * 4);
        uint2 v3 = *(const uint2*)(hn + (size_t)s3 * 128 + lane * 4);
        add_h4(acc, v0); add_h4(acc, v1); add_h4(acc, v2); add_h4(acc, v3);
    }
    for (; j < end; j++) {
        int s = __ldg(&csr[j]);
        add_h4(acc, *(const uint2*)(hn + (size_t)s * 128 + lane * 4));
    }
    acc.x *= di; acc.y *= di; acc.z *= di; acc.w *= di;
    *(float4*)&out[(size_t)row * 128 + lane * 4] = acc;
}

// ---------------------------------------------------------------------------
// CSR gather, layer 2 (F=64, fp32) + final bias/relu, unroll 4
// ---------------------------------------------------------------------------
__global__ __launch_bounds__(256)
void gather64_kernel(const float* __restrict__ hn, const int* __restrict__ offs,
                     const int* __restrict__ csr, const float* __restrict__ dinv,
                     const float* __restrict__ b2, float* __restrict__ out, int N) {
    int warp = (blockIdx.x * 256 + threadIdx.x) >> 5;
    int lane = threadIdx.x & 31;
    if (warp >= N) return;
    const int row = warp;
    int beg = __ldg(&offs[row]);
    int end = __ldg(&offs[row + 1]);
    float di = __ldg(&dinv[row]);

    float2 acc = *(const float2*)&hn[(size_t)row * 64 + lane * 2];   // self-loop
    int j = beg;
    for (; j + 3 < end; j += 4) {
        int s0 = __ldg(&csr[j + 0]);
        int s1 = __ldg(&csr[j + 1]);
        int s2 = __ldg(&csr[j + 2]);
        int s3 = __ldg(&csr[j + 3]);
        float2 v0 = *(const float2*)&hn[(size_t)s0 * 64 + lane * 2];
        float2 v1 = *(const float2*)&hn[(size_t)s1 * 64 + lane * 2];
        float2 v2 = *(const float2*)&hn[(size_t)s2 * 64 + lane * 2];
        float2 v3 = *(const float2*)&hn[(size_t)s3 * 64 + lane * 2];
        acc.x += v0.x + v1.x + v2.x + v3.x;
        acc.y += v0.y + v1.y + v2.y + v3.y;
    }
    for (; j < end; j++) {
        int s = __ldg(&csr[j]);
        float2 v = *(const float2*)&hn[(size_t)s * 64 + lane * 2];
        acc.x += v.x; acc.y += v.y;
    }
    float2 bb = *(const float2*)&b2[lane * 2];
    acc.x = fmaxf(acc.x * di + bb.x, 0.f);
    acc.y = fmaxf(acc.y * di + bb.y, 0.f);
    *(float2*)&out[(size_t)row * 64 + lane * 2] = acc;
}

// ---------------------------------------------------------------------------
extern "C" void kernel_launch(void* const* d_in, const int* in_sizes, int n_in,
                              void* d_out, int out_size) {
    const float* x  = (const float*)d_in[0];
    const int*   ei = (const int*)d_in[1];     // int32 (JAX x64 disabled)
    const float* W1 = (const float*)d_in[2];
    const float* b1 = (const float*)d_in[3];
    const float* W2 = (const float*)d_in[4];
    const float* b2 = (const float*)d_in[5];
    float*       out = (float*)d_out;

    const int N = in_sizes[0] / IN_DIM;
    const int E = in_sizes[1] / 2;
    (void)n_in; (void)out_size;

    void* p;
    cudaGetSymbolAddress(&p, g_h);        float* h    = (float*)p;
    cudaGetSymbolAddress(&p, g_agg);      float* agg  = (float*)p;
    cudaGetSymbolAddress(&p, g_dinv);     float* dinv = (float*)p;
    cudaGetSymbolAddress(&p, g_deg);      int* deg    = (int*)p;
    cudaGetSymbolAddress(&p, g_offs);     int* offs   = (int*)p;
    cudaGetSymbolAddress(&p, g_cursor);   int* cursor = (int*)p;
    cudaGetSymbolAddress(&p, g_csr_src);  int* csr    = (int*)p;
    cudaGetSymbolAddress(&p, g_blocksums);int* bsums  = (int*)p;

    const int* src = ei;
    const int* dst = ei + E;
    const int nb = (N + SCAN_B - 1) / SCAN_B;

    // --- CSR build + normalization (dinv fused into scan) ---
    zero_int_kernel<<<(N + 255) / 256, 256>>>(deg, N);
    deg_kernel<<<(E + 255) / 256, 256>>>(dst, deg, E);
    scan_block_kernel<<<nb, SCAN_B>>>(deg, offs, bsums, dinv, N);
    scan_sums_kernel<<<1, SCAN_B>>>(bsums, nb);
    scan_add_kernel<<<(N + 255) / 256, 256>>>(offs, bsums, cursor, N, E);
    binfill_kernel<<<(E + 255) / 256, 256>>>(src, dst, cursor, csr, E);

    // --- layer 1: hn(fp16) = (x @ W1) * dinv ; agg(fp32) = dinv * (self + gather) ---
    gemm_kernel<128, 128, 4, false, true><<<(N + 63) / 64, 256>>>(x, W1, nullptr, dinv, h, N);
    gather128h_kernel<<<(N * 32 + 255) / 256, 256>>>((const __half*)h, offs, csr, dinv, agg, N);

    // --- layer 2 (fp32): hn2 = (relu(agg + b1) @ W2) * dinv ; out = relu(dinv*(self+gather) + b2) ---
    gemm_kernel<128, 64, 2, true, false><<<(N + 63) / 64, 256>>>(agg, W2, b1, dinv, h, N);
    gather64_kernel<<<(N * 32 + 255) / 256, 256>>>(h, offs, csr, dinv, b2, out, N);
}

// round 8
// speedup vs baseline: 2.4154x; 1.0232x over previous
#include <cuda_runtime.h>
#include <cuda_fp16.h>
#include <cstdint>

#define N_MAX   100000
#define E_MAX   1600000
#define IN_DIM  128
#define SCAN_B  1024

// static scratch (no allocation allowed)
__device__ float g_h[(size_t)N_MAX * 128];     // layer1: fp16 h_norm (N x 128 half); layer2: fp16 h_norm (N x 64 half)
__device__ float g_agg[(size_t)N_MAX * 128];   // layer-1 aggregate (fp32)
__device__ float g_dinv[N_MAX];
__device__ int   g_deg[N_MAX];
__device__ int   g_offs[N_MAX + 1];
__device__ int   g_cursor[N_MAX];
__device__ int   g_csr_src[E_MAX];
__device__ int   g_blocksums[(N_MAX + SCAN_B - 1) / SCAN_B + 1];

// ---------------------------------------------------------------------------
// CSR build: histogram -> scan (fused dinv) -> bin fill
// ---------------------------------------------------------------------------
__global__ void zero_int_kernel(int* __restrict__ p, int n) {
    int i = blockIdx.x * blockDim.x + threadIdx.x;
    if (i < n) p[i] = 0;
}

__global__ void deg_kernel(const int* __restrict__ dst, int* __restrict__ deg, int E) {
    int e = blockIdx.x * blockDim.x + threadIdx.x;
    if (e < E) atomicAdd(&deg[dst[e]], 1);
}

__global__ void scan_block_kernel(const int* __restrict__ deg, int* __restrict__ offs,
                                  int* __restrict__ blocksums, float* __restrict__ dinv, int N) {
    __shared__ int sh[SCAN_B];
    int i = blockIdx.x * SCAN_B + threadIdx.x;
    int v = (i < N) ? deg[i] : 0;
    if (i < N) dinv[i] = rsqrtf((float)(v + 1));        // fused: rsqrt(deg + self-loop)
    sh[threadIdx.x] = v; __syncthreads();
    for (int off = 1; off < SCAN_B; off <<= 1) {
        int t = (threadIdx.x >= off) ? sh[threadIdx.x - off] : 0;
        __syncthreads();
        sh[threadIdx.x] += t;
        __syncthreads();
    }
    if (i < N) offs[i] = sh[threadIdx.x] - v;           // exclusive
    if (threadIdx.x == SCAN_B - 1) blocksums[blockIdx.x] = sh[threadIdx.x];
}

__global__ void scan_sums_kernel(int* __restrict__ blocksums, int nb) {
    __shared__ int sh[SCAN_B];
    int v = (threadIdx.x < nb) ? blocksums[threadIdx.x] : 0;
    sh[threadIdx.x] = v; __syncthreads();
    for (int off = 1; off < SCAN_B; off <<= 1) {
        int t = (threadIdx.x >= off) ? sh[threadIdx.x - off] : 0;
        __syncthreads();
        sh[threadIdx.x] += t;
        __syncthreads();
    }
    if (threadIdx.x < nb) blocksums[threadIdx.x] = sh[threadIdx.x] - v;  // exclusive
}

__global__ void scan_add_kernel(int* __restrict__ offs, const int* __restrict__ blocksums,
                                int* __restrict__ cursor, int N, int E) {
    int i = blockIdx.x * blockDim.x + threadIdx.x;
    if (i < N) {
        int o = offs[i] + blocksums[i / SCAN_B];
        offs[i] = o;
        cursor[i] = o;
    }
    if (i == 0) offs[N] = E;
}

__global__ void binfill_kernel(const int* __restrict__ src, const int* __restrict__ dst,
                               int* __restrict__ cursor, int* __restrict__ csr_src, int E) {
    int e = blockIdx.x * blockDim.x + threadIdx.x;
    if (e < E) {
        int d = dst[e];
        int p = atomicAdd(&cursor[d], 1);
        csr_src[p] = src[e];
    }
}

// ---------------------------------------------------------------------------
// GEMM: C[N,F] = act(A[N,K]) @ W[K,F], epilogue scales row by dinv[row].
//   PRELU: act(a) = relu(a + biasK[k]);  OUTH: emit __half (half2-packed)
// ---------------------------------------------------------------------------
template<int K, int F, int VEC, bool PRELU, bool OUTH>
__global__ __launch_bounds__(256)
void gemm_kernel(const float* __restrict__ A, const float* __restrict__ W,
                 const float* __restrict__ biasK, const float* __restrict__ dinv,
                 void* __restrict__ Cout, int N) {
    __shared__ float xs[64][K];
    const int row0 = blockIdx.x * 64;
    const int tid  = threadIdx.x;

    const int TOT4 = 64 * K / 4;
    for (int i = tid; i < TOT4; i += 256) {
        int fidx = i * 4;
        int r = fidx / K, k = fidx % K;
        float4 v;
        if (row0 + r < N) v = *(const float4*)&A[(size_t)(row0 + r) * K + k];
        else              v = make_float4(0.f, 0.f, 0.f, 0.f);
        if (PRELU) {
            v.x = fmaxf(v.x + biasK[k + 0], 0.f);
            v.y = fmaxf(v.y + biasK[k + 1], 0.f);
            v.z = fmaxf(v.z + biasK[k + 2], 0.f);
            v.w = fmaxf(v.w + biasK[k + 3], 0.f);
        }
        *(float4*)&xs[r][k] = v;
    }
    __syncthreads();

    const int tx = tid & 31;
    const int ty = tid >> 5;

    float acc[8][VEC];
    #pragma unroll
    for (int r = 0; r < 8; r++)
        #pragma unroll
        for (int c = 0; c < VEC; c++) acc[r][c] = 0.f;

    for (int k = 0; k < K; k += 4) {
        float w[4][VEC];
        #pragma unroll
        for (int kk = 0; kk < 4; kk++) {
            if (VEC == 4) {
                float4 t = *(const float4*)&W[(size_t)(k + kk) * F + tx * 4];
                w[kk][0] = t.x; w[kk][1] = t.y; w[kk][2] = t.z; w[kk][3] = t.w;
            } else {
                float2 t = *(const float2*)&W[(size_t)(k + kk) * F + tx * 2];
                w[kk][0] = t.x; w[kk][1] = t.y;
            }
        }
        #pragma unroll
        for (int r = 0; r < 8; r++) {
            float4 xv = *(const float4*)&xs[ty * 8 + r][k];   // broadcast LDS.128
            #pragma unroll
            for (int c = 0; c < VEC; c++) {
                acc[r][c] += xv.x * w[0][c];
                acc[r][c] += xv.y * w[1][c];
                acc[r][c] += xv.z * w[2][c];
                acc[r][c] += xv.w * w[3][c];
            }
        }
    }

    #pragma unroll
    for (int r = 0; r < 8; r++) {
        int row = row0 + ty * 8 + r;
        if (row < N) {
            float di = __ldg(&dinv[row]);
            if (OUTH) {
                if (VEC == 4) {
                    __half2 h0 = __floats2half2_rn(acc[r][0] * di, acc[r][1] * di);
                    __half2 h1 = __floats2half2_rn(acc[r][2] * di, acc[r][3] * di);
                    uint2 st;
                    st.x = *(uint32_t*)&h0;
                    st.y = *(uint32_t*)&h1;
                    *(uint2*)((__half*)Cout + (size_t)row * F + tx * VEC) = st;
                } else {
                    __half2 h0 = __floats2half2_rn(acc[r][0] * di, acc[r][1] * di);
                    *(uint32_t*)((__half*)Cout + (size_t)row * F + tx * VEC) = *(uint32_t*)&h0;
                }
            } else {
                float* C = (float*)Cout;
                #pragma unroll
                for (int c = 0; c < VEC; c++)
                    C[(size_t)row * F + tx * VEC + c] = acc[r][c] * di;
            }
        }
    }
}

// ---------------------------------------------------------------------------
// CSR gather, layer 1 (F=128, fp16 input): agg[d] = dinv[d] * (hn[d] + sum hn[s])
// one warp per node; lane handles 4 halves (8B); fp32 accumulate; unroll 4.
// ---------------------------------------------------------------------------
__device__ __forceinline__ void add_h4(float4& acc, uint2 v) {
    __half2 a = *(__half2*)&v.x;
    __half2 b = *(__half2*)&v.y;
    float2 fa = __half22float2(a);
    float2 fb = __half22float2(b);
    acc.x += fa.x; acc.y += fa.y; acc.z += fb.x; acc.w += fb.y;
}

__global__ __launch_bounds__(256)
void gather128h_kernel(const __half* __restrict__ hn, const int* __restrict__ offs,
                       const int* __restrict__ csr, const float* __restrict__ dinv,
                       float* __restrict__ out, int N) {
    int warp = (blockIdx.x * 256 + threadIdx.x) >> 5;
    int lane = threadIdx.x & 31;
    if (warp >= N) return;
    const int row = warp;
    int beg = __ldg(&offs[row]);
    int end = __ldg(&offs[row + 1]);
    float di = __ldg(&dinv[row]);

    float4 acc = make_float4(0.f, 0.f, 0.f, 0.f);
    add_h4(acc, *(const uint2*)(hn + (size_t)row * 128 + lane * 4));   // self-loop

    int j = beg;
    for (; j + 3 < end; j += 4) {
        int s0 = __ldg(&csr[j + 0]);
        int s1 = __ldg(&csr[j + 1]);
        int s2 = __ldg(&csr[j + 2]);
        int s3 = __ldg(&csr[j + 3]);
        uint2 v0 = *(const uint2*)(hn + (size_t)s0 * 128 + lane * 4);
        uint2 v1 = *(const uint2*)(hn + (size_t)s1 * 128 + lane * 4);
        uint2 v2 = *(const uint2*)(hn + (size_t)s2 * 128 + lane * 4);
        uint2 v3 = *(const uint2*)(hn + (size_t)s3 * 128 + lane * 4);
        add_h4(acc, v0); add_h4(acc, v1); add_h4(acc, v2); add_h4(acc, v3);
    }
    for (; j < end; j++) {
        int s = __ldg(&csr[j]);
        add_h4(acc, *(const uint2*)(hn + (size_t)s * 128 + lane * 4));
    }
    acc.x *= di; acc.y *= di; acc.z *= di; acc.w *= di;
    *(float4*)&out[(size_t)row * 128 + lane * 4] = acc;
}

// ---------------------------------------------------------------------------
// CSR gather, layer 2 (F=64, fp16 input) + final bias/relu:
//   out[d] = relu(dinv[d] * (hn[d] + sum hn[s]) + b2)
// lane handles 2 halves (4B) -> one 128B line per edge per warp; unroll 4.
// ---------------------------------------------------------------------------
__global__ __launch_bounds__(256)
void gather64h_kernel(const __half* __restrict__ hn, const int* __restrict__ offs,
                      const int* __restrict__ csr, const float* __restrict__ dinv,
                      const float* __restrict__ b2, float* __restrict__ out, int N) {
    int warp = (blockIdx.x * 256 + threadIdx.x) >> 5;
    int lane = threadIdx.x & 31;
    if (warp >= N) return;
    const int row = warp;
    int beg = __ldg(&offs[row]);
    int end = __ldg(&offs[row + 1]);
    float di = __ldg(&dinv[row]);

    float2 acc;
    {
        __half2 hv = *(const __half2*)(hn + (size_t)row * 64 + lane * 2);  // self-loop
        acc = __half22float2(hv);
    }
    int j = beg;
    for (; j + 3 < end; j += 4) {
        int s0 = __ldg(&csr[j + 0]);
        int s1 = __ldg(&csr[j + 1]);
        int s2 = __ldg(&csr[j + 2]);
        int s3 = __ldg(&csr[j + 3]);
        __half2 v0 = *(const __half2*)(hn + (size_t)s0 * 64 + lane * 2);
        __half2 v1 = *(const __half2*)(hn + (size_t)s1 * 64 + lane * 2);
        __half2 v2 = *(const __half2*)(hn + (size_t)s2 * 64 + lane * 2);
        __half2 v3 = *(const __half2*)(hn + (size_t)s3 * 64 + lane * 2);
        float2 f0 = __half22float2(v0);
        float2 f1 = __half22float2(v1);
        float2 f2 = __half22float2(v2);
        float2 f3 = __half22float2(v3);
        acc.x += f0.x + f1.x + f2.x + f3.x;
        acc.y += f0.y + f1.y + f2.y + f3.y;
    }
    for (; j < end; j++) {
        int s = __ldg(&csr[j]);
        float2 v = __half22float2(*(const __half2*)(hn + (size_t)s * 64 + lane * 2));
        acc.x += v.x; acc.y += v.y;
    }
    float2 bb = *(const float2*)&b2[lane * 2];
    acc.x = fmaxf(acc.x * di + bb.x, 0.f);
    acc.y = fmaxf(acc.y * di + bb.y, 0.f);
    *(float2*)&out[(size_t)row * 64 + lane * 2] = acc;
}

// ---------------------------------------------------------------------------
extern "C" void kernel_launch(void* const* d_in, const int* in_sizes, int n_in,
                              void* d_out, int out_size) {
    const float* x  = (const float*)d_in[0];
    const int*   ei = (const int*)d_in[1];     // int32 (JAX x64 disabled)
    const float* W1 = (const float*)d_in[2];
    const float* b1 = (const float*)d_in[3];
    const float* W2 = (const float*)d_in[4];
    const float* b2 = (const float*)d_in[5];
    float*       out = (float*)d_out;

    const int N = in_sizes[0] / IN_DIM;
    const int E = in_sizes[1] / 2;
    (void)n_in; (void)out_size;

    void* p;
    cudaGetSymbolAddress(&p, g_h);        float* h    = (float*)p;
    cudaGetSymbolAddress(&p, g_agg);      float* agg  = (float*)p;
    cudaGetSymbolAddress(&p, g_dinv);     float* dinv = (float*)p;
    cudaGetSymbolAddress(&p, g_deg);      int* deg    = (int*)p;
    cudaGetSymbolAddress(&p, g_offs);     int* offs   = (int*)p;
    cudaGetSymbolAddress(&p, g_cursor);   int* cursor = (int*)p;
    cudaGetSymbolAddress(&p, g_csr_src);  int* csr    = (int*)p;
    cudaGetSymbolAddress(&p, g_blocksums);int* bsums  = (int*)p;

    const int* src = ei;
    const int* dst = ei + E;
    const int nb = (N + SCAN_B - 1) / SCAN_B;

    // --- CSR build + normalization (dinv fused into scan) ---
    zero_int_kernel<<<(N + 255) / 256, 256>>>(deg, N);
    deg_kernel<<<(E + 255) / 256, 256>>>(dst, deg, E);
    scan_block_kernel<<<nb, SCAN_B>>>(deg, offs, bsums, dinv, N);
    scan_sums_kernel<<<1, SCAN_B>>>(bsums, nb);
    scan_add_kernel<<<(N + 255) / 256, 256>>>(offs, bsums, cursor, N, E);
    binfill_kernel<<<(E + 255) / 256, 256>>>(src, dst, cursor, csr, E);

    // --- layer 1: hn(fp16) = (x @ W1) * dinv ; agg(fp32) = dinv * (self + gather) ---
    gemm_kernel<128, 128, 4, false, true><<<(N + 63) / 64, 256>>>(x, W1, nullptr, dinv, h, N);
    gather128h_kernel<<<(N * 32 + 255) / 256, 256>>>((const __half*)h, offs, csr, dinv, agg, N);

    // --- layer 2: hn2(fp16) = (relu(agg + b1) @ W2) * dinv ; out = relu(dinv*(self+gather) + b2) ---
    gemm_kernel<128, 64, 2, true, true><<<(N + 63) / 64, 256>>>(agg, W2, b1, dinv, h, N);
    gather64h_kernel<<<(N * 32 + 255) / 256, 256>>>((const __half*)h, offs, csr, dinv, b2, out, N);
}

// round 10
// speedup vs baseline: 2.9078x; 1.2039x over previous
#include <cuda_runtime.h>
#include <cuda_fp16.h>
#include <cstdint>

#define N_MAX   100000
#define E_MAX   1600000
#define IN_DIM  128
#define SCAN_B  1024

// static scratch (no allocation allowed)
__device__ float g_h[(size_t)N_MAX * 128];     // fp16 h_norm per layer (N x 128 / N x 64 half)
__device__ float g_agg[(size_t)N_MAX * 128];   // layer-1 aggregate (fp32)
__device__ float g_dinv[N_MAX];
__device__ int   g_deg[N_MAX];
__device__ int   g_offs[N_MAX + 1];
__device__ int   g_cursor[N_MAX];
__device__ int   g_csr_src[E_MAX];
__device__ int   g_blocksums[(N_MAX + SCAN_B - 1) / SCAN_B + 1];

// ---------------------------------------------------------------------------
// CSR build: histogram -> scan (fused dinv) -> bin fill
// ---------------------------------------------------------------------------
__global__ void zero_int_kernel(int* __restrict__ p, int n) {
    int i = blockIdx.x * blockDim.x + threadIdx.x;
    if (i < n) p[i] = 0;
}

__global__ void deg_kernel(const int* __restrict__ dst, int* __restrict__ deg, int E) {
    int e = blockIdx.x * blockDim.x + threadIdx.x;
    if (e < E) atomicAdd(&deg[dst[e]], 1);
}

__global__ void scan_block_kernel(const int* __restrict__ deg, int* __restrict__ offs,
                                  int* __restrict__ blocksums, float* __restrict__ dinv, int N) {
    __shared__ int sh[SCAN_B];
    int i = blockIdx.x * SCAN_B + threadIdx.x;
    int v = (i < N) ? deg[i] : 0;
    if (i < N) dinv[i] = rsqrtf((float)(v + 1));        // fused: rsqrt(deg + self-loop)
    sh[threadIdx.x] = v; __syncthreads();
    for (int off = 1; off < SCAN_B; off <<= 1) {
        int t = (threadIdx.x >= off) ? sh[threadIdx.x - off] : 0;
        __syncthreads();
        sh[threadIdx.x] += t;
        __syncthreads();
    }
    if (i < N) offs[i] = sh[threadIdx.x] - v;           // exclusive
    if (threadIdx.x == SCAN_B - 1) blocksums[blockIdx.x] = sh[threadIdx.x];
}

__global__ void scan_sums_kernel(int* __restrict__ blocksums, int nb) {
    __shared__ int sh[SCAN_B];
    int v = (threadIdx.x < nb) ? blocksums[threadIdx.x] : 0;
    sh[threadIdx.x] = v; __syncthreads();
    for (int off = 1; off < SCAN_B; off <<= 1) {
        int t = (threadIdx.x >= off) ? sh[threadIdx.x - off] : 0;
        __syncthreads();
        sh[threadIdx.x] += t;
        __syncthreads();
    }
    if (threadIdx.x < nb) blocksums[threadIdx.x] = sh[threadIdx.x] - v;  // exclusive
}

__global__ void scan_add_kernel(int* __restrict__ offs, const int* __restrict__ blocksums,
                                int* __restrict__ cursor, int N, int E) {
    int i = blockIdx.x * blockDim.x + threadIdx.x;
    if (i < N) {
        int o = offs[i] + blocksums[i / SCAN_B];
        offs[i] = o;
        cursor[i] = o;
    }
    if (i == 0) offs[N] = E;
}

__global__ void binfill_kernel(const int* __restrict__ src, const int* __restrict__ dst,
                               int* __restrict__ cursor, int* __restrict__ csr_src, int E) {
    int e = blockIdx.x * blockDim.x + threadIdx.x;
    if (e < E) {
        int d = dst[e];
        int p = atomicAdd(&cursor[d], 1);
        csr_src[p] = src[e];
    }
}

// ---------------------------------------------------------------------------
// Tensor-core GEMM: C[N,F](fp16) = (act(A[N,128]) @ W[128,F]) * dinv[row]
//   mma.sync m16n8k16 fp16 inputs, fp32 accumulate.
//   Block: 128 thr / 4 warps, tile 64 rows. A staged fp16 (fused relu+biasK if
//   PRELU), W staged TRANSPOSED (Ws[n][k]) so A and B fragments are single
//   conflict-free half2 LDS loads (stride 136 halves -> bank = 4g+r, distinct).
// ---------------------------------------------------------------------------
template<int F, bool PRELU>
__global__ __launch_bounds__(128)
void gemm_tc_kernel(const float* __restrict__ A, const float* __restrict__ W,
                    const float* __restrict__ biasK, const float* __restrict__ dinv,
                    __half* __restrict__ C, int N) {
    constexpr int K = 128;
    constexpr int S = K + 8;            // 136-half row stride
    extern __shared__ __half sm[];
    __half* As = sm;                    // [64][S]
    __half* Ws = sm + 64 * S;           // [F][S]  (transposed W)

    const int tid  = threadIdx.x;
    const int row0 = blockIdx.x * 64;

    // stage A: fp32 -> fp16, optional relu(a + biasK[k])
    for (int i = tid * 4; i < 64 * K; i += 128 * 4) {
        int r = i / K, k = i % K;
        float4 v;
        if (row0 + r < N) v = *(const float4*)&A[(size_t)(row0 + r) * K + k];
        else              v = make_float4(0.f, 0.f, 0.f, 0.f);
        if (PRELU) {
            v.x = fmaxf(v.x + biasK[k + 0], 0.f);
            v.y = fmaxf(v.y + biasK[k + 1], 0.f);
            v.z = fmaxf(v.z + biasK[k + 2], 0.f);
            v.w = fmaxf(v.w + biasK[k + 3], 0.f);
        }
        *(__half2*)&As[r * S + k]     = __floats2half2_rn(v.x, v.y);
        *(__half2*)&As[r * S + k + 2] = __floats2half2_rn(v.z, v.w);
    }
    // stage W transposed: Ws[n][k] = W[k][n]
    for (int i = tid; i < K * F; i += 128) {
        int k = i / F, n = i % F;
        Ws[n * S + k] = __float2half(W[i]);
    }
    __syncthreads();

    const int warp = tid >> 5;
    const int lane = tid & 31;
    const int g = lane >> 2;            // 0..7
    const int r = lane & 3;             // 0..3
    const int m0 = warp * 16;

    constexpr int NT = F / 8;
    float c[NT][4];
    #pragma unroll
    for (int nt = 0; nt < NT; nt++) {
        c[nt][0] = 0.f; c[nt][1] = 0.f; c[nt][2] = 0.f; c[nt][3] = 0.f;
    }

    const __half* a0p = &As[(m0 + g) * S + r * 2];
    const __half* a1p = &As[(m0 + g + 8) * S + r * 2];

    #pragma unroll
    for (int ks = 0; ks < 8; ks++) {
        const int k0 = ks * 16;
        uint32_t a0 = *(const uint32_t*)(a0p + k0);
        uint32_t a1 = *(const uint32_t*)(a1p + k0);
        uint32_t a2 = *(const uint32_t*)(a0p + k0 + 8);
        uint32_t a3 = *(const uint32_t*)(a1p + k0 + 8);
        #pragma unroll
        for (int nt = 0; nt < NT; nt++) {
            const __half* bp = &Ws[(nt * 8 + g) * S + r * 2];
            uint32_t b0 = *(const uint32_t*)(bp + k0);
            uint32_t b1 = *(const uint32_t*)(bp + k0 + 8);
            asm volatile(
                "mma.sync.aligned.m16n8k16.row.col.f32.f16.f16.f32 "
                "{%0,%1,%2,%3}, {%4,%5,%6,%7}, {%8,%9}, {%0,%1,%2,%3};"
                : "+f"(c[nt][0]), "+f"(c[nt][1]), "+f"(c[nt][2]), "+f"(c[nt][3])
                : "r"(a0), "r"(a1), "r"(a2), "r"(a3), "r"(b0), "r"(b1));
        }
    }

    // epilogue: scale by dinv, emit fp16
    const int row_a = row0 + m0 + g;
    const int row_b = row_a + 8;
    const float di0 = (row_a < N) ? __ldg(&dinv[row_a]) : 0.f;
    const float di1 = (row_b < N) ? __ldg(&dinv[row_b]) : 0.f;
    #pragma unroll
    for (int nt = 0; nt < NT; nt++) {
        int col = nt * 8 + r * 2;
        if (row_a < N)
            *(__half2*)&C[(size_t)row_a * F + col] = __floats2half2_rn(c[nt][0] * di0, c[nt][1] * di0);
        if (row_b < N)
            *(__half2*)&C[(size_t)row_b * F + col] = __floats2half2_rn(c[nt][2] * di1, c[nt][3] * di1);
    }
}

// ---------------------------------------------------------------------------
// CSR gather, layer 1 (F=128, fp16 input): agg[d] = dinv[d] * (hn[d] + sum hn[s])
// ---------------------------------------------------------------------------
__device__ __forceinline__ void add_h4(float4& acc, uint2 v) {
    __half2 a = *(__half2*)&v.x;
    __half2 b = *(__half2*)&v.y;
    float2 fa = __half22float2(a);
    float2 fb = __half22float2(b);
    acc.x += fa.x; acc.y += fa.y; acc.z += fb.x; acc.w += fb.y;
}

__global__ __launch_bounds__(256)
void gather128h_kernel(const __half* __restrict__ hn, const int* __restrict__ offs,
                       const int* __restrict__ csr, const float* __restrict__ dinv,
                       float* __restrict__ out, int N) {
    int warp = (blockIdx.x * 256 + threadIdx.x) >> 5;
    int lane = threadIdx.x & 31;
    if (warp >= N) return;
    const int row = warp;
    int beg = __ldg(&offs[row]);
    int end = __ldg(&offs[row + 1]);
    float di = __ldg(&dinv[row]);

    float4 acc = make_float4(0.f, 0.f, 0.f, 0.f);
    add_h4(acc, *(const uint2*)(hn + (size_t)row * 128 + lane * 4));   // self-loop

    int j = beg;
    for (; j + 3 < end; j += 4) {
        int s0 = __ldg(&csr[j + 0]);
        int s1 = __ldg(&csr[j + 1]);
        int s2 = __ldg(&csr[j + 2]);
        int s3 = __ldg(&csr[j + 3]);
        uint2 v0 = *(const uint2*)(hn + (size_t)s0 * 128 + lane * 4);
        uint2 v1 = *(const uint2*)(hn + (size_t)s1 * 128 + lane * 4);
        uint2 v2 = *(const uint2*)(hn + (size_t)s2 * 128 + lane * 4);
        uint2 v3 = *(const uint2*)(hn + (size_t)s3 * 128 + lane * 4);
        add_h4(acc, v0); add_h4(acc, v1); add_h4(acc, v2); add_h4(acc, v3);
    }
    for (; j < end; j++) {
        int s = __ldg(&csr[j]);
        add_h4(acc, *(const uint2*)(hn + (size_t)s * 128 + lane * 4));
    }
    acc.x *= di; acc.y *= di; acc.z *= di; acc.w *= di;
    *(float4*)&out[(size_t)row * 128 + lane * 4] = acc;
}

// ---------------------------------------------------------------------------
// CSR gather, layer 2 (F=64, fp16 input) + final bias/relu
// ---------------------------------------------------------------------------
__global__ __launch_bounds__(256)
void gather64h_kernel(const __half* __restrict__ hn, const int* __restrict__ offs,
                      const int* __restrict__ csr, const float* __restrict__ dinv,
                      const float* __restrict__ b2, float* __restrict__ out, int N) {
    int warp = (blockIdx.x * 256 + threadIdx.x) >> 5;
    int lane = threadIdx.x & 31;
    if (warp >= N) return;
    const int row = warp;
    int beg = __ldg(&offs[row]);
    int end = __ldg(&offs[row + 1]);
    float di = __ldg(&dinv[row]);

    float2 acc;
    {
        __half2 hv = *(const __half2*)(hn + (size_t)row * 64 + lane * 2);  // self-loop
        acc = __half22float2(hv);
    }
    int j = beg;
    for (; j + 3 < end; j += 4) {
        int s0 = __ldg(&csr[j + 0]);
        int s1 = __ldg(&csr[j + 1]);
        int s2 = __ldg(&csr[j + 2]);
        int s3 = __ldg(&csr[j + 3]);
        __half2 v0 = *(const __half2*)(hn + (size_t)s0 * 64 + lane * 2);
        __half2 v1 = *(const __half2*)(hn + (size_t)s1 * 64 + lane * 2);
        __half2 v2 = *(const __half2*)(hn + (size_t)s2 * 64 + lane * 2);
        __half2 v3 = *(const __half2*)(hn + (size_t)s3 * 64 + lane * 2);
        float2 f0 = __half22float2(v0);
        float2 f1 = __half22float2(v1);
        float2 f2 = __half22float2(v2);
        float2 f3 = __half22float2(v3);
        acc.x += f0.x + f1.x + f2.x + f3.x;
        acc.y += f0.y + f1.y + f2.y + f3.y;
    }
    for (; j < end; j++) {
        int s = __ldg(&csr[j]);
        float2 v = __half22float2(*(const __half2*)(hn + (size_t)s * 64 + lane * 2));
        acc.x += v.x; acc.y += v.y;
    }
    float2 bb = *(const float2*)&b2[lane * 2];
    acc.x = fmaxf(acc.x * di + bb.x, 0.f);
    acc.y = fmaxf(acc.y * di + bb.y, 0.f);
    *(float2*)&out[(size_t)row * 64 + lane * 2] = acc;
}

// ---------------------------------------------------------------------------
extern "C" void kernel_launch(void* const* d_in, const int* in_sizes, int n_in,
                              void* d_out, int out_size) {
    const float* x  = (const float*)d_in[0];
    const int*   ei = (const int*)d_in[1];     // int32 (JAX x64 disabled)
    const float* W1 = (const float*)d_in[2];
    const float* b1 = (const float*)d_in[3];
    const float* W2 = (const float*)d_in[4];
    const float* b2 = (const float*)d_in[5];
    float*       out = (float*)d_out;

    const int N = in_sizes[0] / IN_DIM;
    const int E = in_sizes[1] / 2;
    (void)n_in; (void)out_size;

    void* p;
    cudaGetSymbolAddress(&p, g_h);        float* h    = (float*)p;
    cudaGetSymbolAddress(&p, g_agg);      float* agg  = (float*)p;
    cudaGetSymbolAddress(&p, g_dinv);     float* dinv = (float*)p;
    cudaGetSymbolAddress(&p, g_deg);      int* deg    = (int*)p;
    cudaGetSymbolAddress(&p, g_offs);     int* offs   = (int*)p;
    cudaGetSymbolAddress(&p, g_cursor);   int* cursor = (int*)p;
    cudaGetSymbolAddress(&p, g_csr_src);  int* csr    = (int*)p;
    cudaGetSymbolAddress(&p, g_blocksums);int* bsums  = (int*)p;

    const int* src = ei;
    const int* dst = ei + E;
    const int nb = (N + SCAN_B - 1) / SCAN_B;

    // dynamic smem sizes for the TC GEMMs ((64 + F) * 136 halves)
    const int smem1 = (64 + 128) * 136 * 2;   // 52224 B -> needs opt-in (>48KB)
    const int smem2 = (64 + 64) * 136 * 2;    // 34816 B
    // idempotent, capture-legal; called unconditionally (no static guards allowed)
    cudaFuncSetAttribute(gemm_tc_kernel<128, false>,
                         cudaFuncAttributeMaxDynamicSharedMemorySize, smem1);
    cudaFuncSetAttribute(gemm_tc_kernel<64, true>,
                         cudaFuncAttributeMaxDynamicSharedMemorySize, smem2);

    // --- CSR build + normalization (dinv fused into scan) ---
    zero_int_kernel<<<(N + 255) / 256, 256>>>(deg, N);
    deg_kernel<<<(E + 255) / 256, 256>>>(dst, deg, E);
    scan_block_kernel<<<nb, SCAN_B>>>(deg, offs, bsums, dinv, N);
    scan_sums_kernel<<<1, SCAN_B>>>(bsums, nb);
    scan_add_kernel<<<(N + 255) / 256, 256>>>(offs, bsums, cursor, N, E);
    binfill_kernel<<<(E + 255) / 256, 256>>>(src, dst, cursor, csr, E);

    // --- layer 1: hn(fp16) = (x @ W1) * dinv ; agg(fp32) = dinv * (self + gather) ---
    gemm_tc_kernel<128, false><<<(N + 63) / 64, 128, smem1>>>(x, W1, nullptr, dinv, (__half*)h, N);
    gather128h_kernel<<<(N * 32 + 255) / 256, 256>>>((const __half*)h, offs, csr, dinv, agg, N);

    // --- layer 2: hn2(fp16) = (relu(agg + b1) @ W2) * dinv ; out = relu(dinv*(self+gather) + b2) ---
    gemm_tc_kernel<64, true><<<(N + 63) / 64, 128, smem2>>>(agg, W2, b1, dinv, (__half*)h, N);
    gather64h_kernel<<<(N * 32 + 255) / 256, 256>>>((const __half*)h, offs, csr, dinv, b2, out, N);
}

// round 11
// speedup vs baseline: 3.0485x; 1.0484x over previous
#include <cuda_runtime.h>
#include <cuda_fp16.h>
#include <cstdint>

#define N_MAX   100000
#define E_MAX   1600000
#define IN_DIM  128
#define SCAN_B  1024
#define NB_MAX  128   // ceil(N_MAX/SCAN_B)=98 <= 128

// static scratch (no allocation allowed)
__device__ float g_h[(size_t)N_MAX * 128];     // fp16 h_norm per layer (N x 128 / N x 64 half)
__device__ float g_agg[(size_t)N_MAX * 128];   // layer-1 aggregate (fp32)
__device__ float g_dinv[N_MAX];
__device__ int   g_deg[N_MAX];
__device__ int   g_offs[N_MAX + 1];
__device__ int   g_cursor[N_MAX];
__device__ int   g_csr_src[E_MAX];
__device__ int   g_blocksums[NB_MAX];

// ---------------------------------------------------------------------------
// CSR build: histogram -> scan (fused dinv) -> bin fill
// ---------------------------------------------------------------------------
__global__ void zero_int_kernel(int* __restrict__ p, int n) {
    int i = blockIdx.x * blockDim.x + threadIdx.x;
    if (i < n) p[i] = 0;
}

__global__ void deg_kernel(const int* __restrict__ dst, int* __restrict__ deg, int E) {
    int e = blockIdx.x * blockDim.x + threadIdx.x;
    if (e < E) atomicAdd(&deg[dst[e]], 1);
}

// 4 edges per thread (requires E % 4 == 0)
__global__ void deg4_kernel(const int* __restrict__ dst, int* __restrict__ deg, int E) {
    int e4 = (blockIdx.x * blockDim.x + threadIdx.x) * 4;
    if (e4 >= E) return;
    int4 d = *(const int4*)&dst[e4];
    atomicAdd(&deg[d.x], 1);
    atomicAdd(&deg[d.y], 1);
    atomicAdd(&deg[d.z], 1);
    atomicAdd(&deg[d.w], 1);
}

__global__ void scan_block_kernel(const int* __restrict__ deg, int* __restrict__ offs,
                                  int* __restrict__ blocksums, float* __restrict__ dinv, int N) {
    __shared__ int sh[SCAN_B];
    int i = blockIdx.x * SCAN_B + threadIdx.x;
    int v = (i < N) ? deg[i] : 0;
    if (i < N) dinv[i] = rsqrtf((float)(v + 1));        // fused: rsqrt(deg + self-loop)
    sh[threadIdx.x] = v; __syncthreads();
    for (int off = 1; off < SCAN_B; off <<= 1) {
        int t = (threadIdx.x >= off) ? sh[threadIdx.x - off] : 0;
        __syncthreads();
        sh[threadIdx.x] += t;
        __syncthreads();
    }
    if (i < N) offs[i] = sh[threadIdx.x] - v;           // exclusive within block
    if (threadIdx.x == SCAN_B - 1) blocksums[blockIdx.x] = sh[threadIdx.x];
}

// folds the (<=128 entry) blocksum scan inline: no separate scan_sums launch
__global__ void scan_add_kernel(int* __restrict__ offs, const int* __restrict__ blocksums,
                                int* __restrict__ cursor, int N, int E, int nb) {
    __shared__ int sh[NB_MAX];
    int t = threadIdx.x;
    if (t < NB_MAX) sh[t] = (t < nb) ? blocksums[t] : 0;
    __syncthreads();
    for (int off = 1; off < NB_MAX; off <<= 1) {
        int v = (t < NB_MAX && t >= off) ? sh[t - off] : 0;
        __syncthreads();
        if (t < NB_MAX) sh[t] += v;                     // inclusive scan
        __syncthreads();
    }
    int i = blockIdx.x * blockDim.x + t;
    if (i < N) {
        int r = i / SCAN_B;
        int pre = (r == 0) ? 0 : sh[r - 1];             // exclusive prefix of region r
        int o = offs[i] + pre;
        offs[i] = o;
        cursor[i] = o;
    }
    if (i == 0) offs[N] = E;
}

__global__ void binfill_kernel(const int* __restrict__ src, const int* __restrict__ dst,
                               int* __restrict__ cursor, int* __restrict__ csr_src, int E) {
    int e = blockIdx.x * blockDim.x + threadIdx.x;
    if (e < E) {
        int d = dst[e];
        int p = atomicAdd(&cursor[d], 1);
        csr_src[p] = src[e];
    }
}

// 4 edges per thread (requires E % 4 == 0)
__global__ void binfill4_kernel(const int* __restrict__ src, const int* __restrict__ dst,
                                int* __restrict__ cursor, int* __restrict__ csr_src, int E) {
    int e4 = (blockIdx.x * blockDim.x + threadIdx.x) * 4;
    if (e4 >= E) return;
    int4 s = *(const int4*)&src[e4];
    int4 d = *(const int4*)&dst[e4];
    csr_src[atomicAdd(&cursor[d.x], 1)] = s.x;
    csr_src[atomicAdd(&cursor[d.y], 1)] = s.y;
    csr_src[atomicAdd(&cursor[d.z], 1)] = s.z;
    csr_src[atomicAdd(&cursor[d.w], 1)] = s.w;
}

// ---------------------------------------------------------------------------
// Tensor-core GEMM: C[N,F](fp16) = (act(A[N,128]) @ W[128,F]) * dinv[row]
//   mma.sync m16n8k16, fp32 accumulate. 128 thr / 4 warps, 64-row tile.
//   W staged TRANSPOSED; conflict-free half2 LDS (136-half stride).
// ---------------------------------------------------------------------------
template<int F, bool PRELU>
__global__ __launch_bounds__(128)
void gemm_tc_kernel(const float* __restrict__ A, const float* __restrict__ W,
                    const float* __restrict__ biasK, const float* __restrict__ dinv,
                    __half* __restrict__ C, int N) {
    constexpr int K = 128;
    constexpr int S = K + 8;            // 136-half row stride
    extern __shared__ __half sm[];
    __half* As = sm;                    // [64][S]
    __half* Ws = sm + 64 * S;           // [F][S]  (transposed W)

    const int tid  = threadIdx.x;
    const int row0 = blockIdx.x * 64;

    for (int i = tid * 4; i < 64 * K; i += 128 * 4) {
        int r = i / K, k = i % K;
        float4 v;
        if (row0 + r < N) v = *(const float4*)&A[(size_t)(row0 + r) * K + k];
        else              v = make_float4(0.f, 0.f, 0.f, 0.f);
        if (PRELU) {
            v.x = fmaxf(v.x + biasK[k + 0], 0.f);
            v.y = fmaxf(v.y + biasK[k + 1], 0.f);
            v.z = fmaxf(v.z + biasK[k + 2], 0.f);
            v.w = fmaxf(v.w + biasK[k + 3], 0.f);
        }
        *(__half2*)&As[r * S + k]     = __floats2half2_rn(v.x, v.y);
        *(__half2*)&As[r * S + k + 2] = __floats2half2_rn(v.z, v.w);
    }
    for (int i = tid; i < K * F; i += 128) {
        int k = i / F, n = i % F;
        Ws[n * S + k] = __float2half(W[i]);
    }
    __syncthreads();

    const int warp = tid >> 5;
    const int lane = tid & 31;
    const int g = lane >> 2;
    const int r = lane & 3;
    const int m0 = warp * 16;

    constexpr int NT = F / 8;
    float c[NT][4];
    #pragma unroll
    for (int nt = 0; nt < NT; nt++) {
        c[nt][0] = 0.f; c[nt][1] = 0.f; c[nt][2] = 0.f; c[nt][3] = 0.f;
    }

    const __half* a0p = &As[(m0 + g) * S + r * 2];
    const __half* a1p = &As[(m0 + g + 8) * S + r * 2];

    #pragma unroll
    for (int ks = 0; ks < 8; ks++) {
        const int k0 = ks * 16;
        uint32_t a0 = *(const uint32_t*)(a0p + k0);
        uint32_t a1 = *(const uint32_t*)(a1p + k0);
        uint32_t a2 = *(const uint32_t*)(a0p + k0 + 8);
        uint32_t a3 = *(const uint32_t*)(a1p + k0 + 8);
        #pragma unroll
        for (int nt = 0; nt < NT; nt++) {
            const __half* bp = &Ws[(nt * 8 + g) * S + r * 2];
            uint32_t b0 = *(const uint32_t*)(bp + k0);
            uint32_t b1 = *(const uint32_t*)(bp + k0 + 8);
            asm volatile(
                "mma.sync.aligned.m16n8k16.row.col.f32.f16.f16.f32 "
                "{%0,%1,%2,%3}, {%4,%5,%6,%7}, {%8,%9}, {%0,%1,%2,%3};"
                : "+f"(c[nt][0]), "+f"(c[nt][1]), "+f"(c[nt][2]), "+f"(c[nt][3])
                : "r"(a0), "r"(a1), "r"(a2), "r"(a3), "r"(b0), "r"(b1));
        }
    }

    const int row_a = row0 + m0 + g;
    const int row_b = row_a + 8;
    const float di0 = (row_a < N) ? __ldg(&dinv[row_a]) : 0.f;
    const float di1 = (row_b < N) ? __ldg(&dinv[row_b]) : 0.f;
    #pragma unroll
    for (int nt = 0; nt < NT; nt++) {
        int col = nt * 8 + r * 2;
        if (row_a < N)
            *(__half2*)&C[(size_t)row_a * F + col] = __floats2half2_rn(c[nt][0] * di0, c[nt][1] * di0);
        if (row_b < N)
            *(__half2*)&C[(size_t)row_b * F + col] = __floats2half2_rn(c[nt][2] * di1, c[nt][3] * di1);
    }
}

// ---------------------------------------------------------------------------
// CSR gather, layer 1 (F=128, fp16): agg[d] = dinv[d] * (hn[d] + sum hn[s])
// one warp per node (32 lanes x 8B = 256B row), unroll 4
// ---------------------------------------------------------------------------
__device__ __forceinline__ void add_h4(float4& acc, uint2 v) {
    __half2 a = *(__half2*)&v.x;
    __half2 b = *(__half2*)&v.y;
    float2 fa = __half22float2(a);
    float2 fb = __half22float2(b);
    acc.x += fa.x; acc.y += fa.y; acc.z += fb.x; acc.w += fb.y;
}

__global__ __launch_bounds__(256)
void gather128h_kernel(const __half* __restrict__ hn, const int* __restrict__ offs,
                       const int* __restrict__ csr, const float* __restrict__ dinv,
                       float* __restrict__ out, int N) {
    int warp = (blockIdx.x * 256 + threadIdx.x) >> 5;
    int lane = threadIdx.x & 31;
    if (warp >= N) return;
    const int row = warp;
    int beg = __ldg(&offs[row]);
    int end = __ldg(&offs[row + 1]);
    float di = __ldg(&dinv[row]);

    float4 acc = make_float4(0.f, 0.f, 0.f, 0.f);
    add_h4(acc, *(const uint2*)(hn + (size_t)row * 128 + lane * 4));   // self-loop

    int j = beg;
    for (; j + 3 < end; j += 4) {
        int s0 = __ldg(&csr[j + 0]);
        int s1 = __ldg(&csr[j + 1]);
        int s2 = __ldg(&csr[j + 2]);
        int s3 = __ldg(&csr[j + 3]);
        uint2 v0 = *(const uint2*)(hn + (size_t)s0 * 128 + lane * 4);
        uint2 v1 = *(const uint2*)(hn + (size_t)s1 * 128 + lane * 4);
        uint2 v2 = *(const uint2*)(hn + (size_t)s2 * 128 + lane * 4);
        uint2 v3 = *(const uint2*)(hn + (size_t)s3 * 128 + lane * 4);
        add_h4(acc, v0); add_h4(acc, v1); add_h4(acc, v2); add_h4(acc, v3);
    }
    for (; j < end; j++) {
        int s = __ldg(&csr[j]);
        add_h4(acc, *(const uint2*)(hn + (size_t)s * 128 + lane * 4));
    }
    acc.x *= di; acc.y *= di; acc.z *= di; acc.w *= di;
    *(float4*)&out[(size_t)row * 128 + lane * 4] = acc;
}

// ---------------------------------------------------------------------------
// CSR gather, layer 2 (F=64, fp16) + final bias/relu.
// TWO nodes per warp: 16 lanes/node, lane covers 4 halves (8B);
// one 128B line per edge; doubles per-warp edge MLP vs 1 node/warp.
// ---------------------------------------------------------------------------
__global__ __launch_bounds__(256)
void gather64h2_kernel(const __half* __restrict__ hn, const int* __restrict__ offs,
                       const int* __restrict__ csr, const float* __restrict__ dinv,
                       const float* __restrict__ b2, float* __restrict__ out, int N) {
    int gid = blockIdx.x * 256 + threadIdx.x;
    int node = gid >> 4;                 // 16 lanes per node
    int l = threadIdx.x & 15;
    if (node >= N) return;
    int beg = __ldg(&offs[node]);
    int end = __ldg(&offs[node + 1]);
    float di = __ldg(&dinv[node]);

    float4 acc = make_float4(0.f, 0.f, 0.f, 0.f);
    add_h4(acc, *(const uint2*)(hn + (size_t)node * 64 + l * 4));     // self-loop

    int j = beg;
    for (; j + 3 < end; j += 4) {
        int s0 = __ldg(&csr[j + 0]);
        int s1 = __ldg(&csr[j + 1]);
        int s2 = __ldg(&csr[j + 2]);
        int s3 = __ldg(&csr[j + 3]);
        uint2 v0 = *(const uint2*)(hn + (size_t)s0 * 64 + l * 4);
        uint2 v1 = *(const uint2*)(hn + (size_t)s1 * 64 + l * 4);
        uint2 v2 = *(const uint2*)(hn + (size_t)s2 * 64 + l * 4);
        uint2 v3 = *(const uint2*)(hn + (size_t)s3 * 64 + l * 4);
        add_h4(acc, v0); add_h4(acc, v1); add_h4(acc, v2); add_h4(acc, v3);
    }
    for (; j < end; j++) {
        int s = __ldg(&csr[j]);
        add_h4(acc, *(const uint2*)(hn + (size_t)s * 64 + l * 4));
    }
    float4 bb = *(const float4*)&b2[l * 4];
    acc.x = fmaxf(acc.x * di + bb.x, 0.f);
    acc.y = fmaxf(acc.y * di + bb.y, 0.f);
    acc.z = fmaxf(acc.z * di + bb.z, 0.f);
    acc.w = fmaxf(acc.w * di + bb.w, 0.f);
    *(float4*)&out[(size_t)node * 64 + l * 4] = acc;
}

// ---------------------------------------------------------------------------
extern "C" void kernel_launch(void* const* d_in, const int* in_sizes, int n_in,
                              void* d_out, int out_size) {
    const float* x  = (const float*)d_in[0];
    const int*   ei = (const int*)d_in[1];     // int32 (JAX x64 disabled)
    const float* W1 = (const float*)d_in[2];
    const float* b1 = (const float*)d_in[3];
    const float* W2 = (const float*)d_in[4];
    const float* b2 = (const float*)d_in[5];
    float*       out = (float*)d_out;

    const int N = in_sizes[0] / IN_DIM;
    const int E = in_sizes[1] / 2;
    (void)n_in; (void)out_size;

    void* p;
    cudaGetSymbolAddress(&p, g_h);        float* h    = (float*)p;
    cudaGetSymbolAddress(&p, g_agg);      float* agg  = (float*)p;
    cudaGetSymbolAddress(&p, g_dinv);     float* dinv = (float*)p;
    cudaGetSymbolAddress(&p, g_deg);      int* deg    = (int*)p;
    cudaGetSymbolAddress(&p, g_offs);     int* offs   = (int*)p;
    cudaGetSymbolAddress(&p, g_cursor);   int* cursor = (int*)p;
    cudaGetSymbolAddress(&p, g_csr_src);  int* csr    = (int*)p;
    cudaGetSymbolAddress(&p, g_blocksums);int* bsums  = (int*)p;

    const int* src = ei;
    const int* dst = ei + E;
    const int nb = (N + SCAN_B - 1) / SCAN_B;
    const bool vec4 = (E % 4 == 0);

    const int smem1 = (64 + 128) * 136 * 2;   // 52224 B -> needs opt-in (>48KB)
    const int smem2 = (64 + 64) * 136 * 2;    // 34816 B
    // idempotent, capture-legal; unconditional (no static guards allowed)
    cudaFuncSetAttribute(gemm_tc_kernel<128, false>,
                         cudaFuncAttributeMaxDynamicSharedMemorySize, smem1);
    cudaFuncSetAttribute(gemm_tc_kernel<64, true>,
                         cudaFuncAttributeMaxDynamicSharedMemorySize, smem2);

    // 1-3: zero, deg histogram, block scan (+dinv)
    zero_int_kernel<<<(N + 255) / 256, 256>>>(deg, N);
    if (vec4) deg4_kernel<<<(E / 4 + 255) / 256, 256>>>(dst, deg, E);
    else      deg_kernel<<<(E + 255) / 256, 256>>>(dst, deg, E);
    scan_block_kernel<<<nb, SCAN_B>>>(deg, offs, bsums, dinv, N);

    // 4: layer-1 GEMM (needs only x, W1, dinv) — 4th launch => ncu profiles it
    gemm_tc_kernel<128, false><<<(N + 63) / 64, 128, smem1>>>(x, W1, nullptr, dinv, (__half*)h, N);

    // 5-6: finish CSR build
    scan_add_kernel<<<(N + 255) / 256, 256>>>(offs, bsums, cursor, N, E, nb);
    if (vec4) binfill4_kernel<<<(E / 4 + 255) / 256, 256>>>(src, dst, cursor, csr, E);
    else      binfill_kernel<<<(E + 255) / 256, 256>>>(src, dst, cursor, csr, E);

    // 7: layer-1 gather
    gather128h_kernel<<<(N * 32 + 255) / 256, 256>>>((const __half*)h, offs, csr, dinv, agg, N);

    // 8-9: layer-2 GEMM (fused relu+b1) + gather (fused bias/relu)
    gemm_tc_kernel<64, true><<<(N + 63) / 64, 128, smem2>>>(agg, W2, b1, dinv, (__half*)h, N);
    gather64h2_kernel<<<(N * 16 + 255) / 256, 256>>>((const __half*)h, offs, csr, dinv, b2, out, N);
}

// round 12
// speedup vs baseline: 3.7374x; 1.2260x over previous
#include <cuda_runtime.h>
#include <cuda_fp16.h>
#include <cstdint>

#define N_MAX   100000
#define E_MAX   1600000
#define IN_DIM  128
#define SCAN_B  1024
#define NB_MAX  128   // ceil(N_MAX/SCAN_B)=98 <= 128

// static scratch (no allocation allowed)
__device__ float  g_h[(size_t)N_MAX * 128];    // fp16 h_norm per layer (N x 128 / N x 64 half)
__device__ float  g_agg[(size_t)N_MAX * 128];  // layer-1 aggregate (fp32)
__device__ float  g_dinv[N_MAX];
__device__ int    g_deg[N_MAX];
__device__ int    g_offs[N_MAX + 1];
__device__ int    g_cursor[N_MAX];
__device__ int    g_csr_src[E_MAX];
__device__ int    g_blocksums[NB_MAX];
__device__ __half g_wt[(128 + 64) * 128];      // fp16 W1^T [128][128] then W2^T [64][128]

// ---------------------------------------------------------------------------
// init: zero deg + pre-transpose/convert W1,W2 to fp16 (k-contiguous rows)
// ---------------------------------------------------------------------------
__global__ void init_kernel(const float* __restrict__ W1, const float* __restrict__ W2,
                            __half* __restrict__ wt, int* __restrict__ deg, int N) {
    int i = blockIdx.x * blockDim.x + threadIdx.x;
    if (i < N) deg[i] = 0;
    if (i < 128 * 128) {
        int n = i >> 7, k = i & 127;
        wt[i] = __float2half(W1[k * 128 + n]);          // w1t[n][k]
    } else if (i < 128 * 128 + 64 * 128) {
        int j = i - 128 * 128;
        int n = j >> 7, k = j & 127;
        wt[128 * 128 + j] = __float2half(W2[k * 64 + n]); // w2t[n][k]
    }
}

// ---------------------------------------------------------------------------
// CSR build: histogram -> scan (fused dinv) -> bin fill
// ---------------------------------------------------------------------------
__global__ void deg_kernel(const int* __restrict__ dst, int* __restrict__ deg, int E) {
    int e = blockIdx.x * blockDim.x + threadIdx.x;
    if (e < E) atomicAdd(&deg[dst[e]], 1);
}

__global__ void deg4_kernel(const int* __restrict__ dst, int* __restrict__ deg, int E) {
    int e4 = (blockIdx.x * blockDim.x + threadIdx.x) * 4;
    if (e4 >= E) return;
    int4 d = *(const int4*)&dst[e4];
    atomicAdd(&deg[d.x], 1);
    atomicAdd(&deg[d.y], 1);
    atomicAdd(&deg[d.z], 1);
    atomicAdd(&deg[d.w], 1);
}

__global__ void scan_block_kernel(const int* __restrict__ deg, int* __restrict__ offs,
                                  int* __restrict__ blocksums, float* __restrict__ dinv, int N) {
    __shared__ int sh[SCAN_B];
    int i = blockIdx.x * SCAN_B + threadIdx.x;
    int v = (i < N) ? deg[i] : 0;
    if (i < N) dinv[i] = rsqrtf((float)(v + 1));        // rsqrt(deg + self-loop)
    sh[threadIdx.x] = v; __syncthreads();
    for (int off = 1; off < SCAN_B; off <<= 1) {
        int t = (threadIdx.x >= off) ? sh[threadIdx.x - off] : 0;
        __syncthreads();
        sh[threadIdx.x] += t;
        __syncthreads();
    }
    if (i < N) offs[i] = sh[threadIdx.x] - v;           // exclusive within block
    if (threadIdx.x == SCAN_B - 1) blocksums[blockIdx.x] = sh[threadIdx.x];
}

// folds the (<=128 entry) blocksum scan inline
__global__ void scan_add_kernel(int* __restrict__ offs, const int* __restrict__ blocksums,
                                int* __restrict__ cursor, int N, int E, int nb) {
    __shared__ int sh[NB_MAX];
    int t = threadIdx.x;
    if (t < NB_MAX) sh[t] = (t < nb) ? blocksums[t] : 0;
    __syncthreads();
    for (int off = 1; off < NB_MAX; off <<= 1) {
        int v = (t < NB_MAX && t >= off) ? sh[t - off] : 0;
        __syncthreads();
        if (t < NB_MAX) sh[t] += v;                     // inclusive
        __syncthreads();
    }
    int i = blockIdx.x * blockDim.x + t;
    if (i < N) {
        int r = i / SCAN_B;
        int pre = (r == 0) ? 0 : sh[r - 1];
        int o = offs[i] + pre;
        offs[i] = o;
        cursor[i] = o;
    }
    if (i == 0) offs[N] = E;
}

__global__ void binfill_kernel(const int* __restrict__ src, const int* __restrict__ dst,
                               int* __restrict__ cursor, int* __restrict__ csr_src, int E) {
    int e = blockIdx.x * blockDim.x + threadIdx.x;
    if (e < E) {
        int d = dst[e];
        int p = atomicAdd(&cursor[d], 1);
        csr_src[p] = src[e];
    }
}

__global__ void binfill4_kernel(const int* __restrict__ src, const int* __restrict__ dst,
                                int* __restrict__ cursor, int* __restrict__ csr_src, int E) {
    int e4 = (blockIdx.x * blockDim.x + threadIdx.x) * 4;
    if (e4 >= E) return;
    int4 s = *(const int4*)&src[e4];
    int4 d = *(const int4*)&dst[e4];
    csr_src[atomicAdd(&cursor[d.x], 1)] = s.x;
    csr_src[atomicAdd(&cursor[d.y], 1)] = s.y;
    csr_src[atomicAdd(&cursor[d.z], 1)] = s.z;
    csr_src[atomicAdd(&cursor[d.w], 1)] = s.w;
}

// ---------------------------------------------------------------------------
// Tensor-core GEMM: C[N,F](fp16) = (act(A[N,128]) @ W[128,F]) * dinv[row]
//   256 thr / 8 warps, 128-row tile. W pre-transposed fp16 in gmem (wt[n][k]),
//   staged to smem via uint4 copies (coalesced, conflict-free). A staged fp16
//   with fused relu+biasK if PRELU. mma.sync m16n8k16, fp32 accumulate.
// ---------------------------------------------------------------------------
template<int F, bool PRELU>
__global__ __launch_bounds__(256)
void gemm_tc_kernel(const float* __restrict__ A, const __half* __restrict__ wt,
                    const float* __restrict__ biasK, const float* __restrict__ dinv,
                    __half* __restrict__ C, int N) {
    constexpr int K = 128;
    constexpr int S = K + 8;            // 136-half row stride
    extern __shared__ __half sm[];
    __half* As = sm;                    // [128][S]
    __half* Ws = sm + 128 * S;          // [F][S]  (wt rows, k-contiguous)

    const int tid  = threadIdx.x;
    const int row0 = blockIdx.x * 128;

    // stage A: fp32 -> fp16, optional relu(a + biasK[k]); 128 rows
    for (int i = tid * 4; i < 128 * K; i += 256 * 4) {
        int r = i / K, k = i % K;
        float4 v;
        if (row0 + r < N) v = *(const float4*)&A[(size_t)(row0 + r) * K + k];
        else              v = make_float4(0.f, 0.f, 0.f, 0.f);
        if (PRELU) {
            v.x = fmaxf(v.x + biasK[k + 0], 0.f);
            v.y = fmaxf(v.y + biasK[k + 1], 0.f);
            v.z = fmaxf(v.z + biasK[k + 2], 0.f);
            v.w = fmaxf(v.w + biasK[k + 3], 0.f);
        }
        *(__half2*)&As[r * S + k]     = __floats2half2_rn(v.x, v.y);
        *(__half2*)&As[r * S + k + 2] = __floats2half2_rn(v.z, v.w);
    }
    // stage W: uint4 copy (8 halves), wt already transposed+fp16
    for (int idx = tid; idx < F * K / 8; idx += 256) {
        int n = (idx * 8) / K, k = (idx * 8) % K;
        *(uint4*)&Ws[n * S + k] = *(const uint4*)&wt[n * K + k];
    }
    __syncthreads();

    const int warp = tid >> 5;
    const int lane = tid & 31;
    const int g = lane >> 2;
    const int r = lane & 3;
    const int m0 = warp * 16;           // 8 warps x 16 rows = 128

    constexpr int NT = F / 8;
    float c[NT][4];
    #pragma unroll
    for (int nt = 0; nt < NT; nt++) {
        c[nt][0] = 0.f; c[nt][1] = 0.f; c[nt][2] = 0.f; c[nt][3] = 0.f;
    }

    const __half* a0p = &As[(m0 + g) * S + r * 2];
    const __half* a1p = &As[(m0 + g + 8) * S + r * 2];

    #pragma unroll
    for (int ks = 0; ks < 8; ks++) {
        const int k0 = ks * 16;
        uint32_t a0 = *(const uint32_t*)(a0p + k0);
        uint32_t a1 = *(const uint32_t*)(a1p + k0);
        uint32_t a2 = *(const uint32_t*)(a0p + k0 + 8);
        uint32_t a3 = *(const uint32_t*)(a1p + k0 + 8);
        #pragma unroll
        for (int nt = 0; nt < NT; nt++) {
            const __half* bp = &Ws[(nt * 8 + g) * S + r * 2];
            uint32_t b0 = *(const uint32_t*)(bp + k0);
            uint32_t b1 = *(const uint32_t*)(bp + k0 + 8);
            asm volatile(
                "mma.sync.aligned.m16n8k16.row.col.f32.f16.f16.f32 "
                "{%0,%1,%2,%3}, {%4,%5,%6,%7}, {%8,%9}, {%0,%1,%2,%3};"
                : "+f"(c[nt][0]), "+f"(c[nt][1]), "+f"(c[nt][2]), "+f"(c[nt][3])
                : "r"(a0), "r"(a1), "r"(a2), "r"(a3), "r"(b0), "r"(b1));
        }
    }

    const int row_a = row0 + m0 + g;
    const int row_b = row_a + 8;
    const float di0 = (row_a < N) ? __ldg(&dinv[row_a]) : 0.f;
    const float di1 = (row_b < N) ? __ldg(&dinv[row_b]) : 0.f;
    #pragma unroll
    for (int nt = 0; nt < NT; nt++) {
        int col = nt * 8 + r * 2;
        if (row_a < N)
            *(__half2*)&C[(size_t)row_a * F + col] = __floats2half2_rn(c[nt][0] * di0, c[nt][1] * di0);
        if (row_b < N)
            *(__half2*)&C[(size_t)row_b * F + col] = __floats2half2_rn(c[nt][2] * di1, c[nt][3] * di1);
    }
}

// ---------------------------------------------------------------------------
// CSR gather, layer 1 (F=128, fp16): agg[d] = dinv[d] * (hn[d] + sum hn[s])
// ---------------------------------------------------------------------------
__device__ __forceinline__ void add_h4(float4& acc, uint2 v) {
    __half2 a = *(__half2*)&v.x;
    __half2 b = *(__half2*)&v.y;
    float2 fa = __half22float2(a);
    float2 fb = __half22float2(b);
    acc.x += fa.x; acc.y += fa.y; acc.z += fb.x; acc.w += fb.y;
}

__global__ __launch_bounds__(256)
void gather128h_kernel(const __half* __restrict__ hn, const int* __restrict__ offs,
                       const int* __restrict__ csr, const float* __restrict__ dinv,
                       float* __restrict__ out, int N) {
    int warp = (blockIdx.x * 256 + threadIdx.x) >> 5;
    int lane = threadIdx.x & 31;
    if (warp >= N) return;
    const int row = warp;
    int beg = __ldg(&offs[row]);
    int end = __ldg(&offs[row + 1]);
    float di = __ldg(&dinv[row]);

    float4 acc = make_float4(0.f, 0.f, 0.f, 0.f);
    add_h4(acc, *(const uint2*)(hn + (size_t)row * 128 + lane * 4));   // self-loop

    int j = beg;
    for (; j + 3 < end; j += 4) {
        int s0 = __ldg(&csr[j + 0]);
        int s1 = __ldg(&csr[j + 1]);
        int s2 = __ldg(&csr[j + 2]);
        int s3 = __ldg(&csr[j + 3]);
        uint2 v0 = *(const uint2*)(hn + (size_t)s0 * 128 + lane * 4);
        uint2 v1 = *(const uint2*)(hn + (size_t)s1 * 128 + lane * 4);
        uint2 v2 = *(const uint2*)(hn + (size_t)s2 * 128 + lane * 4);
        uint2 v3 = *(const uint2*)(hn + (size_t)s3 * 128 + lane * 4);
        add_h4(acc, v0); add_h4(acc, v1); add_h4(acc, v2); add_h4(acc, v3);
    }
    for (; j < end; j++) {
        int s = __ldg(&csr[j]);
        add_h4(acc, *(const uint2*)(hn + (size_t)s * 128 + lane * 4));
    }
    acc.x *= di; acc.y *= di; acc.z *= di; acc.w *= di;
    *(float4*)&out[(size_t)row * 128 + lane * 4] = acc;
}

// ---------------------------------------------------------------------------
// CSR gather, layer 2 (F=64, fp16) + final bias/relu. Two nodes per warp.
// ---------------------------------------------------------------------------
__global__ __launch_bounds__(256)
void gather64h2_kernel(const __half* __restrict__ hn, const int* __restrict__ offs,
                       const int* __restrict__ csr, const float* __restrict__ dinv,
                       const float* __restrict__ b2, float* __restrict__ out, int N) {
    int gid = blockIdx.x * 256 + threadIdx.x;
    int node = gid >> 4;                 // 16 lanes per node
    int l = threadIdx.x & 15;
    if (node >= N) return;
    int beg = __ldg(&offs[node]);
    int end = __ldg(&offs[node + 1]);
    float di = __ldg(&dinv[node]);

    float4 acc = make_float4(0.f, 0.f, 0.f, 0.f);
    add_h4(acc, *(const uint2*)(hn + (size_t)node * 64 + l * 4));     // self-loop

    int j = beg;
    for (; j + 3 < end; j += 4) {
        int s0 = __ldg(&csr[j + 0]);
        int s1 = __ldg(&csr[j + 1]);
        int s2 = __ldg(&csr[j + 2]);
        int s3 = __ldg(&csr[j + 3]);
        uint2 v0 = *(const uint2*)(hn + (size_t)s0 * 64 + l * 4);
        uint2 v1 = *(const uint2*)(hn + (size_t)s1 * 64 + l * 4);
        uint2 v2 = *(const uint2*)(hn + (size_t)s2 * 64 + l * 4);
        uint2 v3 = *(const uint2*)(hn + (size_t)s3 * 64 + l * 4);
        add_h4(acc, v0); add_h4(acc, v1); add_h4(acc, v2); add_h4(acc, v3);
    }
    for (; j < end; j++) {
        int s = __ldg(&csr[j]);
        add_h4(acc, *(const uint2*)(hn + (size_t)s * 64 + l * 4));
    }
    float4 bb = *(const float4*)&b2[l * 4];
    acc.x = fmaxf(acc.x * di + bb.x, 0.f);
    acc.y = fmaxf(acc.y * di + bb.y, 0.f);
    acc.z = fmaxf(acc.z * di + bb.z, 0.f);
    acc.w = fmaxf(acc.w * di + bb.w, 0.f);
    *(float4*)&out[(size_t)node * 64 + l * 4] = acc;
}

// ---------------------------------------------------------------------------
extern "C" void kernel_launch(void* const* d_in, const int* in_sizes, int n_in,
                              void* d_out, int out_size) {
    const float* x  = (const float*)d_in[0];
    const int*   ei = (const int*)d_in[1];     // int32 (JAX x64 disabled)
    const float* W1 = (const float*)d_in[2];
    const float* b1 = (const float*)d_in[3];
    const float* W2 = (const float*)d_in[4];
    const float* b2 = (const float*)d_in[5];
    float*       out = (float*)d_out;

    const int N = in_sizes[0] / IN_DIM;
    const int E = in_sizes[1] / 2;
    (void)n_in; (void)out_size;

    void* p;
    cudaGetSymbolAddress(&p, g_h);        float*  h    = (float*)p;
    cudaGetSymbolAddress(&p, g_agg);      float*  agg  = (float*)p;
    cudaGetSymbolAddress(&p, g_dinv);     float*  dinv = (float*)p;
    cudaGetSymbolAddress(&p, g_deg);      int*    deg  = (int*)p;
    cudaGetSymbolAddress(&p, g_offs);     int*    offs = (int*)p;
    cudaGetSymbolAddress(&p, g_cursor);   int*    cursor = (int*)p;
    cudaGetSymbolAddress(&p, g_csr_src);  int*    csr  = (int*)p;
    cudaGetSymbolAddress(&p, g_blocksums);int*    bsums = (int*)p;
    cudaGetSymbolAddress(&p, g_wt);       __half* wt   = (__half*)p;

    const int* src = ei;
    const int* dst = ei + E;
    const int nb = (N + SCAN_B - 1) / SCAN_B;
    const bool vec4 = (E % 4 == 0);

    const int smem1 = (128 + 128) * 136 * 2;   // 69632 B
    const int smem2 = (128 + 64) * 136 * 2;    // 52224 B
    // idempotent, capture-legal; unconditional (no static guards allowed)
    cudaFuncSetAttribute(gemm_tc_kernel<128, false>,
                         cudaFuncAttributeMaxDynamicSharedMemorySize, smem1);
    cudaFuncSetAttribute(gemm_tc_kernel<64, true>,
                         cudaFuncAttributeMaxDynamicSharedMemorySize, smem2);

    // 1-3: init (zero deg + W->fp16 transpose), deg histogram, block scan (+dinv)
    init_kernel<<<(N + 255) / 256, 256>>>(W1, W2, wt, deg, N);
    if (vec4) deg4_kernel<<<(E / 4 + 255) / 256, 256>>>(dst, deg, E);
    else      deg_kernel<<<(E + 255) / 256, 256>>>(dst, deg, E);
    scan_block_kernel<<<nb, SCAN_B>>>(deg, offs, bsums, dinv, N);

    // 4: layer-1 GEMM — 4th launch => ncu profiles it
    gemm_tc_kernel<128, false><<<(N + 127) / 128, 256, smem1>>>(x, wt, nullptr, dinv, (__half*)h, N);

    // 5-6: finish CSR build
    scan_add_kernel<<<(N + 255) / 256, 256>>>(offs, bsums, cursor, N, E, nb);
    if (vec4) binfill4_kernel<<<(E / 4 + 255) / 256, 256>>>(src, dst, cursor, csr, E);
    else      binfill_kernel<<<(E + 255) / 256, 256>>>(src, dst, cursor, csr, E);

    // 7: layer-1 gather
    gather128h_kernel<<<(N * 32 + 255) / 256, 256>>>((const __half*)h, offs, csr, dinv, agg, N);

    // 8-9: layer-2 GEMM (fused relu+b1) + gather (fused bias/relu)
    gemm_tc_kernel<64, true><<<(N + 127) / 128, 256, smem2>>>(agg, wt + 128 * 128, b1, dinv, (__half*)h, N);
    gather64h2_kernel<<<(N * 16 + 255) / 256, 256>>>((const __half*)h, offs, csr, dinv, b2, out, N);
}

// round 14
// speedup vs baseline: 3.9881x; 1.0671x over previous
#include <cuda_runtime.h>
#include <cuda_fp16.h>
#include <cstdint>

#define N_MAX   100000
#define E_MAX   1600000
#define IN_DIM  128
#define SCAN_B  1024
#define NB_MAX  128   // ceil(N_MAX/SCAN_B)=98 <= 128

// static scratch (no allocation allowed)
__device__ float  g_h[(size_t)N_MAX * 128];    // fp16 h_norm per layer
__device__ float  g_agg[(size_t)N_MAX * 128];  // layer-1 aggregate (fp32)
__device__ float  g_dinv[N_MAX];
__device__ int    g_deg[N_MAX];
__device__ int    g_offs[N_MAX + 1];
__device__ int    g_cursor[N_MAX];
__device__ int    g_csr_src[E_MAX];
__device__ int    g_blocksums[NB_MAX];
// fragment-ordered fp16 weights: layer1 8ks*16nt*32lanes uint2, layer2 8ks*8nt*32 uint2
__device__ uint2  g_fw[8 * 16 * 32 + 8 * 8 * 32];

// ---------------------------------------------------------------------------
// init: zero deg + build fragment-ordered fp16 W for both layers.
// fw[ks][nt][lane] = { h2(W[k0+r*2][n], W[k0+r*2+1][n]),
//                      h2(W[k0+r*2+8][n], W[k0+r*2+9][n]) },
// n = nt*8 + (lane>>2), r = lane&3, k0 = ks*16.  (mma m16n8k16 B layout)
// ---------------------------------------------------------------------------
__global__ void init_kernel(const float* __restrict__ W1, const float* __restrict__ W2,
                            uint2* __restrict__ fw, int* __restrict__ deg, int N) {
    int i = blockIdx.x * blockDim.x + threadIdx.x;
    if (i < N) deg[i] = 0;
    const int C1 = 8 * 16 * 32;          // layer-1 fragment count
    const int C2 = 8 * 8 * 32;
    if (i < C1) {
        int ks = i / (16 * 32), rem = i % (16 * 32);
        int nt = rem / 32, lane = rem % 32;
        int g = lane >> 2, r = lane & 3;
        int n = nt * 8 + g, k = ks * 16 + r * 2;
        __half2 b0 = __floats2half2_rn(W1[k * 128 + n],       W1[(k + 1) * 128 + n]);
        __half2 b1 = __floats2half2_rn(W1[(k + 8) * 128 + n], W1[(k + 9) * 128 + n]);
        uint2 u; u.x = *(uint32_t*)&b0; u.y = *(uint32_t*)&b1;
        fw[i] = u;
    } else if (i < C1 + C2) {
        int j = i - C1;
        int ks = j / (8 * 32), rem = j % (8 * 32);
        int nt = rem / 32, lane = rem % 32;
        int g = lane >> 2, r = lane & 3;
        int n = nt * 8 + g, k = ks * 16 + r * 2;
        __half2 b0 = __floats2half2_rn(W2[k * 64 + n],       W2[(k + 1) * 64 + n]);
        __half2 b1 = __floats2half2_rn(W2[(k + 8) * 64 + n], W2[(k + 9) * 64 + n]);
        uint2 u; u.x = *(uint32_t*)&b0; u.y = *(uint32_t*)&b1;
        fw[C1 + j] = u;
    }
}

// ---------------------------------------------------------------------------
// CSR build
// ---------------------------------------------------------------------------
__global__ void deg_kernel(const int* __restrict__ dst, int* __restrict__ deg, int E) {
    int e = blockIdx.x * blockDim.x + threadIdx.x;
    if (e < E) atomicAdd(&deg[dst[e]], 1);
}

__global__ void deg4_kernel(const int* __restrict__ dst, int* __restrict__ deg, int E) {
    int e4 = (blockIdx.x * blockDim.x + threadIdx.x) * 4;
    if (e4 >= E) return;
    int4 d = *(const int4*)&dst[e4];
    atomicAdd(&deg[d.x], 1);
    atomicAdd(&deg[d.y], 1);
    atomicAdd(&deg[d.z], 1);
    atomicAdd(&deg[d.w], 1);
}

__global__ void scan_block_kernel(const int* __restrict__ deg, int* __restrict__ offs,
                                  int* __restrict__ blocksums, float* __restrict__ dinv, int N) {
    __shared__ int sh[SCAN_B];
    int i = blockIdx.x * SCAN_B + threadIdx.x;
    int v = (i < N) ? deg[i] : 0;
    if (i < N) dinv[i] = rsqrtf((float)(v + 1));
    sh[threadIdx.x] = v; __syncthreads();
    for (int off = 1; off < SCAN_B; off <<= 1) {
        int t = (threadIdx.x >= off) ? sh[threadIdx.x - off] : 0;
        __syncthreads();
        sh[threadIdx.x] += t;
        __syncthreads();
    }
    if (i < N) offs[i] = sh[threadIdx.x] - v;
    if (threadIdx.x == SCAN_B - 1) blocksums[blockIdx.x] = sh[threadIdx.x];
}

__global__ void scan_add_kernel(int* __restrict__ offs, const int* __restrict__ blocksums,
                                int* __restrict__ cursor, int N, int E, int nb) {
    __shared__ int sh[NB_MAX];
    int t = threadIdx.x;
    if (t < NB_MAX) sh[t] = (t < nb) ? blocksums[t] : 0;
    __syncthreads();
    for (int off = 1; off < NB_MAX; off <<= 1) {
        int v = (t < NB_MAX && t >= off) ? sh[t - off] : 0;
        __syncthreads();
        if (t < NB_MAX) sh[t] += v;
        __syncthreads();
    }
    int i = blockIdx.x * blockDim.x + t;
    if (i < N) {
        int r = i / SCAN_B;
        int pre = (r == 0) ? 0 : sh[r - 1];
        int o = offs[i] + pre;
        offs[i] = o;
        cursor[i] = o;
    }
    if (i == 0) offs[N] = E;
}

__global__ void binfill_kernel(const int* __restrict__ src, const int* __restrict__ dst,
                               int* __restrict__ cursor, int* __restrict__ csr_src, int E) {
    int e = blockIdx.x * blockDim.x + threadIdx.x;
    if (e < E) {
        int d = dst[e];
        int p = atomicAdd(&cursor[d], 1);
        csr_src[p] = src[e];
    }
}

__global__ void binfill4_kernel(const int* __restrict__ src, const int* __restrict__ dst,
                                int* __restrict__ cursor, int* __restrict__ csr_src, int E) {
    int e4 = (blockIdx.x * blockDim.x + threadIdx.x) * 4;
    if (e4 >= E) return;
    int4 s = *(const int4*)&src[e4];
    int4 d = *(const int4*)&dst[e4];
    csr_src[atomicAdd(&cursor[d.x], 1)] = s.x;
    csr_src[atomicAdd(&cursor[d.y], 1)] = s.y;
    csr_src[atomicAdd(&cursor[d.z], 1)] = s.z;
    csr_src[atomicAdd(&cursor[d.w], 1)] = s.w;
}

// ---------------------------------------------------------------------------
// Smem-free tensor-core GEMM: C[N,F](fp16) = (act(A[N,128]) @ W) * dinv[row]
//   A fragments loaded directly from fp32 gmem (float2 + cvt, fused PRELU);
//   W fragments via single L1-resident LDG.64 from fragment-ordered gmem.
//   No smem, no __syncthreads. 256 thr / 8 warps.
//   CSPLIT: warps per row-group (col split). rows/block = (8/CSPLIT)*16.
// ---------------------------------------------------------------------------
template<int F, int CSPLIT, bool PRELU>
__global__ __launch_bounds__(256)
void gemm_tc_kernel(const float* __restrict__ A, const uint2* __restrict__ fw,
                    const float* __restrict__ biasK, const float* __restrict__ dinv,
                    __half* __restrict__ C, int N) {
    constexpr int K = 128;
    constexpr int NTT = F / 8;           // total n-tiles
    constexpr int NT = NTT / CSPLIT;     // n-tiles per warp
    constexpr int ROWS = (8 / CSPLIT) * 16;

    const int tid  = threadIdx.x;
    const int warp = tid >> 5;
    const int lane = tid & 31;
    const int g = lane >> 2;
    const int r = lane & 3;
    const int rowgrp = warp / CSPLIT;
    const int colgrp = warp % CSPLIT;

    const int row_a = blockIdx.x * ROWS + rowgrp * 16 + g;
    const int row_b = row_a + 8;
    const int ra = (row_a < N) ? row_a : N - 1;   // clamp; stores are guarded
    const int rb = (row_b < N) ? row_b : N - 1;
    const float* Aa = A + (size_t)ra * K;
    const float* Ab = A + (size_t)rb * K;

    float c[NT][4];
    #pragma unroll
    for (int nt = 0; nt < NT; nt++) {
        c[nt][0] = 0.f; c[nt][1] = 0.f; c[nt][2] = 0.f; c[nt][3] = 0.f;
    }

    #pragma unroll
    for (int ks = 0; ks < 8; ks++) {
        const int k0 = ks * 16;
        float2 va0 = *(const float2*)&Aa[k0 + r * 2];
        float2 va1 = *(const float2*)&Aa[k0 + r * 2 + 8];
        float2 vb0 = *(const float2*)&Ab[k0 + r * 2];
        float2 vb1 = *(const float2*)&Ab[k0 + r * 2 + 8];
        if (PRELU) {
            float2 q0 = *(const float2*)&biasK[k0 + r * 2];
            float2 q1 = *(const float2*)&biasK[k0 + r * 2 + 8];
            va0.x = fmaxf(va0.x + q0.x, 0.f); va0.y = fmaxf(va0.y + q0.y, 0.f);
            va1.x = fmaxf(va1.x + q1.x, 0.f); va1.y = fmaxf(va1.y + q1.y, 0.f);
            vb0.x = fmaxf(vb0.x + q0.x, 0.f); vb0.y = fmaxf(vb0.y + q0.y, 0.f);
            vb1.x = fmaxf(vb1.x + q1.x, 0.f); vb1.y = fmaxf(vb1.y + q1.y, 0.f);
        }
        __half2 h0 = __floats2half2_rn(va0.x, va0.y);
        __half2 h1 = __floats2half2_rn(vb0.x, vb0.y);
        __half2 h2 = __floats2half2_rn(va1.x, va1.y);
        __half2 h3 = __floats2half2_rn(vb1.x, vb1.y);
        uint32_t a0 = *(uint32_t*)&h0;
        uint32_t a1 = *(uint32_t*)&h1;
        uint32_t a2 = *(uint32_t*)&h2;
        uint32_t a3 = *(uint32_t*)&h3;

        const uint2* fwk = fw + ((size_t)ks * NTT + colgrp * NT) * 32 + lane;
        #pragma unroll
        for (int nt = 0; nt < NT; nt++) {
            uint2 b = __ldg(&fwk[nt * 32]);
            asm volatile(
                "mma.sync.aligned.m16n8k16.row.col.f32.f16.f16.f32 "
                "{%0,%1,%2,%3}, {%4,%5,%6,%7}, {%8,%9}, {%0,%1,%2,%3};"
                : "+f"(c[nt][0]), "+f"(c[nt][1]), "+f"(c[nt][2]), "+f"(c[nt][3])
                : "r"(a0), "r"(a1), "r"(a2), "r"(a3), "r"(b.x), "r"(b.y));
        }
    }

    const float di0 = (row_a < N) ? __ldg(&dinv[row_a]) : 0.f;
    const float di1 = (row_b < N) ? __ldg(&dinv[row_b]) : 0.f;
    const int colbase = colgrp * (F / CSPLIT);
    #pragma unroll
    for (int nt = 0; nt < NT; nt++) {
        int col = colbase + nt * 8 + r * 2;
        if (row_a < N)
            *(__half2*)&C[(size_t)row_a * F + col] = __floats2half2_rn(c[nt][0] * di0, c[nt][1] * di0);
        if (row_b < N)
            *(__half2*)&C[(size_t)row_b * F + col] = __floats2half2_rn(c[nt][2] * di1, c[nt][3] * di1);
    }
}

// ---------------------------------------------------------------------------
// CSR gather, layer 1 (F=128, fp16): agg[d] = dinv[d] * (hn[d] + sum hn[s])
// ---------------------------------------------------------------------------
__device__ __forceinline__ void add_h4(float4& acc, uint2 v) {
    __half2 a = *(__half2*)&v.x;
    __half2 b = *(__half2*)&v.y;
    float2 fa = __half22float2(a);
    float2 fb = __half22float2(b);
    acc.x += fa.x; acc.y += fa.y; acc.z += fb.x; acc.w += fb.y;
}

__global__ __launch_bounds__(256)
void gather128h_kernel(const __half* __restrict__ hn, const int* __restrict__ offs,
                       const int* __restrict__ csr, const float* __restrict__ dinv,
                       float* __restrict__ out, int N) {
    int warp = (blockIdx.x * 256 + threadIdx.x) >> 5;
    int lane = threadIdx.x & 31;
    if (warp >= N) return;
    const int row = warp;
    int beg = __ldg(&offs[row]);
    int end = __ldg(&offs[row + 1]);
    float di = __ldg(&dinv[row]);

    float4 acc = make_float4(0.f, 0.f, 0.f, 0.f);
    add_h4(acc, *(const uint2*)(hn + (size_t)row * 128 + lane * 4));   // self-loop

    int j = beg;
    for (; j + 3 < end; j += 4) {
        int s0 = __ldg(&csr[j + 0]);
        int s1 = __ldg(&csr[j + 1]);
        int s2 = __ldg(&csr[j + 2]);
        int s3 = __ldg(&csr[j + 3]);
        uint2 v0 = *(const uint2*)(hn + (size_t)s0 * 128 + lane * 4);
        uint2 v1 = *(const uint2*)(hn + (size_t)s1 * 128 + lane * 4);
        uint2 v2 = *(const uint2*)(hn + (size_t)s2 * 128 + lane * 4);
        uint2 v3 = *(const uint2*)(hn + (size_t)s3 * 128 + lane * 4);
        add_h4(acc, v0); add_h4(acc, v1); add_h4(acc, v2); add_h4(acc, v3);
    }
    for (; j < end; j++) {
        int s = __ldg(&csr[j]);
        add_h4(acc, *(const uint2*)(hn + (size_t)s * 128 + lane * 4));
    }
    acc.x *= di; acc.y *= di; acc.z *= di; acc.w *= di;
    *(float4*)&out[(size_t)row * 128 + lane * 4] = acc;
}

// ---------------------------------------------------------------------------
// CSR gather, layer 2 (F=64, fp16) + final bias/relu. Two nodes per warp.
// ---------------------------------------------------------------------------
__global__ __launch_bounds__(256)
void gather64h2_kernel(const __half* __restrict__ hn, const int* __restrict__ offs,
                       const int* __restrict__ csr, const float* __restrict__ dinv,
                       const float* __restrict__ b2, float* __restrict__ out, int N) {
    int gid = blockIdx.x * 256 + threadIdx.x;
    int node = gid >> 4;                 // 16 lanes per node
    int l = threadIdx.x & 15;
    if (node >= N) return;
    int beg = __ldg(&offs[node]);
    int end = __ldg(&offs[node + 1]);
    float di = __ldg(&dinv[node]);

    float4 acc = make_float4(0.f, 0.f, 0.f, 0.f);
    add_h4(acc, *(const uint2*)(hn + (size_t)node * 64 + l * 4));     // self-loop

    int j = beg;
    for (; j + 3 < end; j += 4) {
        int s0 = __ldg(&csr[j + 0]);
        int s1 = __ldg(&csr[j + 1]);
        int s2 = __ldg(&csr[j + 2]);
        int s3 = __ldg(&csr[j + 3]);
        uint2 v0 = *(const uint2*)(hn + (size_t)s0 * 64 + l * 4);
        uint2 v1 = *(const uint2*)(hn + (size_t)s1 * 64 + l * 4);
        uint2 v2 = *(const uint2*)(hn + (size_t)s2 * 64 + l * 4);
        uint2 v3 = *(const uint2*)(hn + (size_t)s3 * 64 + l * 4);
        add_h4(acc, v0); add_h4(acc, v1); add_h4(acc, v2); add_h4(acc, v3);
    }
    for (; j < end; j++) {
        int s = __ldg(&csr[j]);
        add_h4(acc, *(const uint2*)(hn + (size_t)s * 64 + l * 4));
    }
    float4 bb = *(const float4*)&b2[l * 4];
    acc.x = fmaxf(acc.x * di + bb.x, 0.f);
    acc.y = fmaxf(acc.y * di + bb.y, 0.f);
    acc.z = fmaxf(acc.z * di + bb.z, 0.f);
    acc.w = fmaxf(acc.w * di + bb.w, 0.f);
    *(float4*)&out[(size_t)node * 64 + l * 4] = acc;
}

// ---------------------------------------------------------------------------
extern "C" void kernel_launch(void* const* d_in, const int* in_sizes, int n_in,
                              void* d_out, int out_size) {
    const float* x  = (const float*)d_in[0];
    const int*   ei = (const int*)d_in[1];     // int32 (JAX x64 disabled)
    const float* W1 = (const float*)d_in[2];
    const float* b1 = (const float*)d_in[3];
    const float* W2 = (const float*)d_in[4];
    const float* b2 = (const float*)d_in[5];
    float*       out = (float*)d_out;

    const int N = in_sizes[0] / IN_DIM;
    const int E = in_sizes[1] / 2;
    (void)n_in; (void)out_size;

    void* p;
    cudaGetSymbolAddress(&p, g_h);        float* h    = (float*)p;
    cudaGetSymbolAddress(&p, g_agg);      float* agg  = (float*)p;
    cudaGetSymbolAddress(&p, g_dinv);     float* dinv = (float*)p;
    cudaGetSymbolAddress(&p, g_deg);      int*   deg  = (int*)p;
    cudaGetSymbolAddress(&p, g_offs);     int*   offs = (int*)p;
    cudaGetSymbolAddress(&p, g_cursor);   int*   cursor = (int*)p;
    cudaGetSymbolAddress(&p, g_csr_src);  int*   csr  = (int*)p;
    cudaGetSymbolAddress(&p, g_blocksums);int*   bsums = (int*)p;
    cudaGetSymbolAddress(&p, g_fw);       uint2* fw   = (uint2*)p;

    const int* src = ei;
    const int* dst = ei + E;
    const int nb = (N + SCAN_B - 1) / SCAN_B;
    const bool vec4 = (E % 4 == 0);
    const int C1 = 8 * 16 * 32;          // layer-1 fragment words

    // 1-3: init (zero deg + fragment-ordered W), deg histogram, block scan (+dinv)
    init_kernel<<<(N + 255) / 256, 256>>>(W1, W2, fw, deg, N);
    if (vec4) deg4_kernel<<<(E / 4 + 255) / 256, 256>>>(dst, deg, E);
    else      deg_kernel<<<(E + 255) / 256, 256>>>(dst, deg, E);
    scan_block_kernel<<<nb, SCAN_B>>>(deg, offs, bsums, dinv, N);

    // 4: layer-1 GEMM (CSPLIT=2: 64 rows/block) — 4th launch => ncu profiles it
    gemm_tc_kernel<128, 2, false><<<(N + 63) / 64, 256>>>(x, fw, nullptr, dinv, (__half*)h, N);

    // 5-6: finish CSR build
    scan_add_kernel<<<(N + 255) / 256, 256>>>(offs, bsums, cursor, N, E, nb);
    if (vec4) binfill4_kernel<<<(E / 4 + 255) / 256, 256>>>(src, dst, cursor, csr, E);
    else      binfill_kernel<<<(E + 255) / 256, 256>>>(src, dst, cursor, csr, E);

    // 7: layer-1 gather
    gather128h_kernel<<<(N * 32 + 255) / 256, 256>>>((const __half*)h, offs, csr, dinv, agg, N);

    // 8-9: layer-2 GEMM (CSPLIT=1: 128 rows/block, fused relu+b1) + gather
    gemm_tc_kernel<64, 1, true><<<(N + 127) / 128, 256>>>(agg, fw + C1, b1, dinv, (__half*)h, N);
    gather64h2_kernel<<<(N * 16 + 255) / 256, 256>>>((const __half*)h, offs, csr, dinv, b2, out, N);
}